// round 6
// baseline (speedup 1.0000x reference)
#include <cuda_runtime.h>
#include <math.h>

// Problem constants (match reference setup_inputs)
#define NSRC   200000
#define NF     128
#define NH     1500
#define NC     64
#define R0     50000
#define R1     10000

// ---------------- scratch: small statics only (total ~44 MB) ----------------
__device__ float d_xmean[R0 * NF];   // 25.6 MB: neighbor sums, normalized in place
__device__ float d_cnt0f[R0];
__device__ float d_g[R0 * NC];       // 12.8 MB: g = h @ W2_neigh (accumulated)
__device__ float d_yroot[R1 * NC];   //  2.6 MB: h[:R1] @ W2_root (accumulated)
__device__ float d_gsum[R1 * NC];
__device__ float d_cnt1f[R1];
__device__ int   d_emax[4];

// ---------------- zero all accumulators (every call; graph replays) ---------
__global__ void zero_kernel() {
    int i = blockIdx.x * blockDim.x + threadIdx.x;
    if (i < R0 * NF) d_xmean[i] = 0.f;
    if (i < R0 * NC) d_g[i] = 0.f;
    if (i < R1 * NC) { d_yroot[i] = 0.f; d_gsum[i] = 0.f; }
    if (i < R0)      d_cnt0f[i] = 0.f;
    if (i < R1)      d_cnt1f[i] = 0.f;
    if (i < 4)       d_emax[i] = 0;
}

// max of two candidate edge arrays -> d_emax[slot], d_emax[slot+1]
__global__ void edgemax_kernel(const int* __restrict__ a,
                               const int* __restrict__ b, int n, int slot) {
    __shared__ int sa, sb;
    if (threadIdx.x == 0) { sa = 0; sb = 0; }
    __syncthreads();
    int i = blockIdx.x * blockDim.x + threadIdx.x;
    int va = 0, vb = 0;
    for (; i < n; i += gridDim.x * blockDim.x) { va = max(va, a[i]); vb = max(vb, b[i]); }
    atomicMax(&sa, va);
    atomicMax(&sb, vb);
    __syncthreads();
    if (threadIdx.x == 0) { atomicMax(&d_emax[slot], sa); atomicMax(&d_emax[slot + 1], sb); }
}

// ---------------- layer-1 edge-parallel mean aggregation --------------------
__global__ void agg1_kernel(const float* __restrict__ x,
                            const int* __restrict__ ea,
                            const int* __restrict__ eb, int E) {
    int gid  = blockIdx.x * blockDim.x + threadIdx.x;
    int e    = gid >> 5;
    int lane = gid & 31;
    if (e >= E) return;
    bool a_is_src = d_emax[0] >= d_emax[1];
    int s = a_is_src ? ea[e] : eb[e];
    int t = a_is_src ? eb[e] : ea[e];
    if ((unsigned)s >= NSRC || (unsigned)t >= R0) return;  // defensive
    float4 v = *reinterpret_cast<const float4*>(x + (size_t)s * NF + lane * 4);
    float* dst = d_xmean + (size_t)t * NF + lane * 4;
    atomicAdd(dst + 0, v.x);
    atomicAdd(dst + 1, v.y);
    atomicAdd(dst + 2, v.z);
    atomicAdd(dst + 3, v.w);
    if (lane == 0) atomicAdd(&d_cnt0f[t], 1.0f);
}

__global__ void norm1_kernel() {
    int i = blockIdx.x * blockDim.x + threadIdx.x;
    if (i >= R0 * NF) return;
    int r = i >> 7;
    d_xmean[i] = d_xmean[i] / fmaxf(d_cnt0f[r], 1.f);
}

// ---------------- fused: h-tile = relu([x|xmean]@[W1r;W1n]+b1), then --------
// ---------------- project: d_g += h@W2n, d_yroot += h[:R1]@W2r --------------
// M=50000, N=1500, K=256. BM=64, BN=64, BK=16, 256 threads, 4x4/thread.
__global__ __launch_bounds__(256) void fused1_kernel(
    const float* __restrict__ x,   const float* __restrict__ W1r,
    const float* __restrict__ W1n, const float* __restrict__ b1,
    const float* __restrict__ W2r, const float* __restrict__ W2n) {
    __shared__ float As[16][64];
    __shared__ float Bs[16][64];
    __shared__ float Hs[64][65];
    int tid = threadIdx.x;
    int m0 = blockIdx.y * 64;
    int n0 = blockIdx.x * 64;
    int ty = tid >> 4, tx = tid & 15;

    float acc[4][4];
#pragma unroll
    for (int i = 0; i < 4; i++)
#pragma unroll
        for (int j = 0; j < 4; j++) acc[i][j] = 0.f;

    for (int k0 = 0; k0 < 256; k0 += 16) {
        const float* Asrc = (k0 < 128) ? (x + k0) : (d_xmean + (k0 - 128));
        const float* Bsrc = (k0 < 128) ? (W1r + (size_t)k0 * NH)
                                       : (W1n + (size_t)(k0 - 128) * NH);
        {   // A: 64 rows x 16 k; one float4 along k per thread
            int m  = tid >> 2;
            int kq = tid & 3;
            int gm = m0 + m;
            float4 v = make_float4(0.f, 0.f, 0.f, 0.f);
            if (gm < R0)
                v = *reinterpret_cast<const float4*>(Asrc + (size_t)gm * NF + kq * 4);
            As[kq * 4 + 0][m] = v.x;
            As[kq * 4 + 1][m] = v.y;
            As[kq * 4 + 2][m] = v.z;
            As[kq * 4 + 3][m] = v.w;
        }
        {   // B: 16 k x 64 cols; one float4 along n per thread
            int kk = tid >> 4;
            int nq = tid & 15;
            int gn = n0 + nq * 4;
            float4 v = make_float4(0.f, 0.f, 0.f, 0.f);
            if (gn < NH)   // NH and gn both multiples of 4 -> fully valid
                v = *reinterpret_cast<const float4*>(Bsrc + (size_t)kk * NH + gn);
            Bs[kk][nq * 4 + 0] = v.x;
            Bs[kk][nq * 4 + 1] = v.y;
            Bs[kk][nq * 4 + 2] = v.z;
            Bs[kk][nq * 4 + 3] = v.w;
        }
        __syncthreads();
#pragma unroll
        for (int kk = 0; kk < 16; kk++) {
            float a[4], b[4];
#pragma unroll
            for (int i = 0; i < 4; i++) a[i] = As[kk][ty * 4 + i];
#pragma unroll
            for (int j = 0; j < 4; j++) b[j] = Bs[kk][tx * 4 + j];
#pragma unroll
            for (int i = 0; i < 4; i++)
#pragma unroll
                for (int j = 0; j < 4; j++) acc[i][j] += a[i] * b[j];
        }
        __syncthreads();
    }

    // bias + relu -> Hs (zero outside valid range)
#pragma unroll
    for (int i = 0; i < 4; i++) {
        int gm = m0 + ty * 4 + i;
#pragma unroll
        for (int j = 0; j < 4; j++) {
            int gn = n0 + tx * 4 + j;
            float hv = 0.f;
            if (gm < R0 && gn < NH) hv = fmaxf(acc[i][j] + b1[gn], 0.f);
            Hs[ty * 4 + i][tx * 4 + j] = hv;
        }
    }
    __syncthreads();

    // projection epilogue: thread -> (m = tid>>2, 16 cols at (tid&3)*16)
    {
        int m  = tid >> 2;
        int cq = (tid & 3) * 16;
        int gm = m0 + m;
        int nlim = min(64, NH - n0);
        bool do_r = (m0 < R1);
        float accn[16], accr[16];
#pragma unroll
        for (int c = 0; c < 16; c++) { accn[c] = 0.f; accr[c] = 0.f; }
        for (int n = 0; n < nlim; n++) {
            float hv = Hs[m][n];
            const float* wn = W2n + (size_t)(n0 + n) * NC + cq;
#pragma unroll
            for (int c = 0; c < 16; c++) accn[c] += hv * wn[c];
            if (do_r) {
                const float* wr = W2r + (size_t)(n0 + n) * NC + cq;
#pragma unroll
                for (int c = 0; c < 16; c++) accr[c] += hv * wr[c];
            }
        }
        if (gm < R0) {
            float* dst = d_g + (size_t)gm * NC + cq;
#pragma unroll
            for (int c = 0; c < 16; c++) atomicAdd(dst + c, accn[c]);
        }
        if (do_r && gm < R1) {
            float* dst = d_yroot + (size_t)gm * NC + cq;
#pragma unroll
            for (int c = 0; c < 16; c++) atomicAdd(dst + c, accr[c]);
        }
    }
}

// ---------------- layer-2 edge-parallel aggregation of g --------------------
__global__ void agg2_kernel(const int* __restrict__ ea,
                            const int* __restrict__ eb, int E) {
    int gid  = blockIdx.x * blockDim.x + threadIdx.x;
    int e    = gid >> 5;
    int lane = gid & 31;
    if (e >= E) return;
    bool a_is_src = d_emax[2] >= d_emax[3];
    int s = a_is_src ? ea[e] : eb[e];
    int t = a_is_src ? eb[e] : ea[e];
    if ((unsigned)s >= R0 || (unsigned)t >= R1) return;  // defensive
    float2 v = *reinterpret_cast<const float2*>(d_g + (size_t)s * NC + lane * 2);
    atomicAdd(&d_gsum[t * NC + lane * 2 + 0], v.x);
    atomicAdd(&d_gsum[t * NC + lane * 2 + 1], v.y);
    if (lane == 0) atomicAdd(&d_cnt1f[t], 1.0f);
}

// ---------------- final: logits = yroot + gsum/cnt + b2; log_softmax --------
__global__ void final_kernel(const float* __restrict__ b2, float* __restrict__ out) {
    int gid  = blockIdx.x * blockDim.x + threadIdx.x;
    int w    = gid >> 5;
    int lane = gid & 31;
    if (w >= R1) return;
    float inv = 1.f / fmaxf(d_cnt1f[w], 1.f);
    float vx = d_gsum[w * NC + lane * 2 + 0] * inv
             + d_yroot[w * NC + lane * 2 + 0] + b2[lane * 2 + 0];
    float vy = d_gsum[w * NC + lane * 2 + 1] * inv
             + d_yroot[w * NC + lane * 2 + 1] + b2[lane * 2 + 1];
    float m = fmaxf(vx, vy);
#pragma unroll
    for (int o = 16; o; o >>= 1) m = fmaxf(m, __shfl_xor_sync(0xffffffffu, m, o));
    float s = expf(vx - m) + expf(vy - m);
#pragma unroll
    for (int o = 16; o; o >>= 1) s += __shfl_xor_sync(0xffffffffu, s, o);
    float lse = logf(s);
    out[w * NC + lane * 2 + 0] = vx - m - lse;
    out[w * NC + lane * 2 + 1] = vy - m - lse;
}

// ---------------- launch ----------------------------------------------------
extern "C" void kernel_launch(void* const* d_in, const int* in_sizes, int n_in,
                              void* d_out, int out_size) {
    // identify every input by its unique element count
    const float *x = 0, *W1r = 0, *W1n = 0, *b1 = 0, *W2r = 0, *W2n = 0, *b2 = 0;
    const int *eA0 = 0, *eB0 = 0, *eA1 = 0, *eB1 = 0;
    for (int i = 0; i < n_in; i++) {
        int sz = in_sizes[i];
        const void* p = d_in[i];
        if      (sz == NSRC * NF) { x = (const float*)p; }
        else if (sz == NF * NH)   { if (!W1r) W1r = (const float*)p; else W1n = (const float*)p; }
        else if (sz == NH)        { b1 = (const float*)p; }
        else if (sz == NH * NC)   { if (!W2r) W2r = (const float*)p; else W2n = (const float*)p; }
        else if (sz == NC)        { b2 = (const float*)p; }
        else if (sz == 1600000)   { if (!eA0) eA0 = (const int*)p; else eB0 = (const int*)p; }
        else if (sz == 500000)    { if (!eA1) eA1 = (const int*)p; else eB1 = (const int*)p; }
    }
    const int E0 = 1600000, E1 = 500000;
    float* out = (float*)d_out;
    (void)out_size;

    zero_kernel<<<(R0 * NF + 255) / 256, 256>>>();

    edgemax_kernel<<<256, 256>>>(eA0, eB0, E0, 0);
    edgemax_kernel<<<256, 256>>>(eA1, eB1, E1, 2);

    agg1_kernel<<<((size_t)E0 * 32 + 255) / 256, 256>>>(x, eA0, eB0, E0);
    norm1_kernel<<<(R0 * NF + 255) / 256, 256>>>();

    // fused GEMM1 + W2 projection epilogue (no 300MB h buffer, no gemm2)
    dim3 g1((NH + 63) / 64, (R0 + 63) / 64);
    fused1_kernel<<<g1, 256>>>(x, W1r, W1n, b1, W2r, W2n);

    agg2_kernel<<<((size_t)E1 * 32 + 255) / 256, 256>>>(eA1, eB1, E1);

    final_kernel<<<(R1 * 32 + 255) / 256, 256>>>(b2, out);
}

// round 8
// speedup vs baseline: 2.1199x; 2.1199x over previous
#include <cuda_runtime.h>
#include <cuda_bf16.h>
#include <math.h>

// Problem constants (match reference setup_inputs)
#define NSRC   200000
#define NF     128
#define NH     1500
#define NC     64
#define R0     50000
#define R1     10000
#define NHPAD  1536
#define MTILES 391
#define MROWS  (MTILES * 128)   // 50048
#define NT     24               // N-slabs of 64 covering 1500 (padded to 1536)

// ---------------- scratch (__device__ globals; no allocation allowed) --------
__device__ float d_xmean[R0 * NF];            // 25.6 MB
__device__ float d_cnt0f[R0];
__device__ float d_g[R0 * NC];                // 12.8 MB
__device__ float d_yroot[R1 * NC];
__device__ float d_gsum[R1 * NC];
__device__ float d_cnt1f[R1];
__device__ int   d_emax[4];
__device__ __nv_bfloat16 d_Ab[(size_t)MROWS * 256];   // 25.6 MB  [x | xmean] bf16
__device__ __nv_bfloat16 d_W1b[NHPAD * 256];          // [n][k] = W1{r,n}[k][n]
__device__ __nv_bfloat16 d_W2nb[NC * NHPAD];          // [c][n] = W2n[n][c]
__device__ __nv_bfloat16 d_W2rb[NC * NHPAD];          // [c][n] = W2r[n][c]

// ---------------- zero accumulators (every call; graph replays) -------------
__global__ void zero_kernel() {
    int i = blockIdx.x * blockDim.x + threadIdx.x;
    if (i < R0 * NF) d_xmean[i] = 0.f;
    if (i < R1 * NC) d_gsum[i] = 0.f;
    if (i < R0)      d_cnt0f[i] = 0.f;
    if (i < R1)      d_cnt1f[i] = 0.f;
    if (i < 4)       d_emax[i] = 0;
}

__global__ void edgemax_kernel(const int* __restrict__ a,
                               const int* __restrict__ b, int n, int slot) {
    __shared__ int sa, sb;
    if (threadIdx.x == 0) { sa = 0; sb = 0; }
    __syncthreads();
    int i = blockIdx.x * blockDim.x + threadIdx.x;
    int va = 0, vb = 0;
    for (; i < n; i += gridDim.x * blockDim.x) { va = max(va, a[i]); vb = max(vb, b[i]); }
    atomicMax(&sa, va);
    atomicMax(&sb, vb);
    __syncthreads();
    if (threadIdx.x == 0) { atomicMax(&d_emax[slot], sa); atomicMax(&d_emax[slot + 1], sb); }
}

// ---------------- layer-1 edge-parallel mean aggregation --------------------
__global__ void agg1_kernel(const float* __restrict__ x,
                            const int* __restrict__ ea,
                            const int* __restrict__ eb, int E) {
    int gid  = blockIdx.x * blockDim.x + threadIdx.x;
    int e    = gid >> 5;
    int lane = gid & 31;
    if (e >= E) return;
    bool a_is_src = d_emax[0] >= d_emax[1];
    int s = a_is_src ? ea[e] : eb[e];
    int t = a_is_src ? eb[e] : ea[e];
    if ((unsigned)s >= NSRC || (unsigned)t >= R0) return;
    float4 v = *reinterpret_cast<const float4*>(x + (size_t)s * NF + lane * 4);
    float* dst = d_xmean + (size_t)t * NF + lane * 4;
    atomicAdd(dst + 0, v.x);
    atomicAdd(dst + 1, v.y);
    atomicAdd(dst + 2, v.z);
    atomicAdd(dst + 3, v.w);
    if (lane == 0) atomicAdd(&d_cnt0f[t], 1.0f);
}

__global__ void norm1_kernel() {
    int i = blockIdx.x * blockDim.x + threadIdx.x;
    if (i >= R0 * NF) return;
    int r = i >> 7;
    d_xmean[i] = d_xmean[i] / fmaxf(d_cnt0f[r], 1.f);
}

// ---------------- bf16 operand preparation ----------------------------------
__global__ void convA_kernel(const float* __restrict__ x) {
    size_t i = (size_t)blockIdx.x * blockDim.x + threadIdx.x;
    if (i >= (size_t)MROWS * 256) return;
    int m = (int)(i >> 8), k = (int)(i & 255);
    float v = 0.f;
    if (m < R0) v = (k < 128) ? x[(size_t)m * NF + k] : d_xmean[(size_t)m * NF + (k - 128)];
    d_Ab[i] = __float2bfloat16(v);
}
__global__ void convW1_kernel(const float* __restrict__ W1r, const float* __restrict__ W1n) {
    int i = blockIdx.x * blockDim.x + threadIdx.x;
    if (i >= NHPAD * 256) return;
    int n = i >> 8, k = i & 255;
    float v = 0.f;
    if (n < NH) v = (k < 128) ? W1r[(size_t)k * NH + n] : W1n[(size_t)(k - 128) * NH + n];
    d_W1b[i] = __float2bfloat16(v);
}
__global__ void convW2_kernel(const float* __restrict__ W2n, const float* __restrict__ W2r) {
    int i = blockIdx.x * blockDim.x + threadIdx.x;
    if (i >= NC * NHPAD) return;
    int c = i / NHPAD, n = i % NHPAD;
    float vn = 0.f, vr = 0.f;
    if (n < NH) { vn = W2n[(size_t)n * NC + c]; vr = W2r[(size_t)n * NC + c]; }
    d_W2nb[i] = __float2bfloat16(vn);
    d_W2rb[i] = __float2bfloat16(vr);
}

// ---------------- HMMA helpers ----------------------------------------------
__device__ __forceinline__ void mma16816(float* c, unsigned a0, unsigned a1,
                                         unsigned a2, unsigned a3,
                                         unsigned b0, unsigned b1) {
    asm volatile(
        "mma.sync.aligned.m16n8k16.row.col.f32.bf16.bf16.f32 "
        "{%0,%1,%2,%3}, {%4,%5,%6,%7}, {%8,%9}, {%0,%1,%2,%3};"
        : "+f"(c[0]), "+f"(c[1]), "+f"(c[2]), "+f"(c[3])
        : "r"(a0), "r"(a1), "r"(a2), "r"(a3), "r"(b0), "r"(b1));
}
__device__ __forceinline__ unsigned pack_bf16(float lo, float hi) {
    unsigned r;
    asm("cvt.rn.bf16x2.f32 %0, %1, %2;" : "=r"(r) : "f"(hi), "f"(lo));
    return r;
}

// ---------------- fused GEMM chain on HMMA tensor cores ---------------------
// One CTA = 128 M-rows, 8 warps x 16 rows. Loop 24 hidden-slabs of 64:
//   MMA1: Hacc(16x64) = A(16x256) @ W1slab(64x256)^T   (B frags from global/L1)
//   bias+relu -> convert D-frags DIRECTLY to A-frags (register-only, no SMEM H)
//   MMA2/3: accG += H @ W2n_slab, accY += H @ W2r_slab (persistent reg accums)
// Store d_g / d_yroot densely at the end. Zero atomics, zero slab-loop syncs.
#define APITCH 264   // bf16 units; 528B rows -> conflict-free frag loads

__global__ __launch_bounds__(256) void mma_fused_kernel(const float* __restrict__ b1) {
    extern __shared__ __nv_bfloat16 As[];   // [128][APITCH]
    int tid  = threadIdx.x;
    int warp = tid >> 5;
    int lane = tid & 31;
    int g    = lane >> 2;     // 0..7
    int tig  = lane & 3;      // 0..3
    int m0   = blockIdx.x * 128;
    int mrow = warp * 16;

    // stage A tile (128 x 256 bf16) into padded SMEM
    for (int idx = tid; idx < 128 * 32; idx += 256) {
        int row = idx >> 5, c8 = idx & 31;
        uint4 v = reinterpret_cast<const uint4*>(d_Ab + (size_t)(m0 + row) * 256)[c8];
        *reinterpret_cast<uint4*>(&As[row * APITCH + c8 * 8]) = v;
    }
    __syncthreads();

    float accG[8][4], accY[8][4];
#pragma unroll
    for (int j = 0; j < 8; j++)
#pragma unroll
        for (int q = 0; q < 4; q++) { accG[j][q] = 0.f; accY[j][q] = 0.f; }

    const bool doY = (m0 < R1);

    for (int it = 0; it < NT; it++) {
        int n0 = it * 64;
        float accH[8][4];
#pragma unroll
        for (int j = 0; j < 8; j++)
#pragma unroll
            for (int q = 0; q < 4; q++) accH[j][q] = 0.f;

        // ---- MMA1: K=256 in 16 steps ----
#pragma unroll 4
        for (int kk = 0; kk < 16; kk++) {
            int kb = kk * 16;
            unsigned a0 = *reinterpret_cast<unsigned*>(&As[(mrow + g)     * APITCH + kb + tig * 2]);
            unsigned a1 = *reinterpret_cast<unsigned*>(&As[(mrow + g + 8) * APITCH + kb + tig * 2]);
            unsigned a2 = *reinterpret_cast<unsigned*>(&As[(mrow + g)     * APITCH + kb + 8 + tig * 2]);
            unsigned a3 = *reinterpret_cast<unsigned*>(&As[(mrow + g + 8) * APITCH + kb + 8 + tig * 2]);
#pragma unroll
            for (int j = 0; j < 8; j++) {
                const __nv_bfloat16* bp = d_W1b + (size_t)(n0 + j * 8 + g) * 256 + kb;
                unsigned b0 = *reinterpret_cast<const unsigned*>(bp + tig * 2);
                unsigned b1f = *reinterpret_cast<const unsigned*>(bp + 8 + tig * 2);
                mma16816(accH[j], a0, a1, a2, a3, b0, b1f);
            }
        }

        // ---- bias + relu -> bf16 A-frags for projection (register-only) ----
        unsigned hfrag[4][4];   // [k-step 0..3][a0..a3]
#pragma unroll
        for (int j = 0; j < 8; j++) {
            int c0 = n0 + j * 8 + tig * 2;
            float bb0 = (c0     < NH) ? __ldg(b1 + c0)     : 0.f;
            float bb1 = (c0 + 1 < NH) ? __ldg(b1 + c0 + 1) : 0.f;
            float h0 = (c0     < NH) ? fmaxf(accH[j][0] + bb0, 0.f) : 0.f;
            float h1 = (c0 + 1 < NH) ? fmaxf(accH[j][1] + bb1, 0.f) : 0.f;
            float h2 = (c0     < NH) ? fmaxf(accH[j][2] + bb0, 0.f) : 0.f;
            float h3 = (c0 + 1 < NH) ? fmaxf(accH[j][3] + bb1, 0.f) : 0.f;
            // D-frag (rows g,g+8; cols tig*2,+1) == half of an A-frag layout
            hfrag[j >> 1][(j & 1) * 2 + 0] = pack_bf16(h0, h1);   // rows g
            hfrag[j >> 1][(j & 1) * 2 + 1] = pack_bf16(h2, h3);   // rows g+8
        }

        // ---- MMA2/MMA3: accumulate projections, K=64 slab in 4 steps ----
#pragma unroll
        for (int kk = 0; kk < 4; kk++) {
            int kb = n0 + kk * 16;
            unsigned a0 = hfrag[kk][0], a1 = hfrag[kk][1];
            unsigned a2 = hfrag[kk][2], a3 = hfrag[kk][3];
#pragma unroll
            for (int j = 0; j < 8; j++) {
                const __nv_bfloat16* bp = d_W2nb + (size_t)(j * 8 + g) * NHPAD + kb;
                unsigned b0 = *reinterpret_cast<const unsigned*>(bp + tig * 2);
                unsigned b1f = *reinterpret_cast<const unsigned*>(bp + 8 + tig * 2);
                mma16816(accG[j], a0, a1, a2, a3, b0, b1f);
            }
            if (doY) {
#pragma unroll
                for (int j = 0; j < 8; j++) {
                    const __nv_bfloat16* bp = d_W2rb + (size_t)(j * 8 + g) * NHPAD + kb;
                    unsigned b0 = *reinterpret_cast<const unsigned*>(bp + tig * 2);
                    unsigned b1f = *reinterpret_cast<const unsigned*>(bp + 8 + tig * 2);
                    mma16816(accY[j], a0, a1, a2, a3, b0, b1f);
                }
            }
        }
    }

    // ---- dense store: G rows m0+mrow+g(+8), cols j*8+tig*2 ----
    {
        int gmA = m0 + mrow + g;
        int gmB = gmA + 8;
#pragma unroll
        for (int j = 0; j < 8; j++) {
            int c = j * 8 + tig * 2;
            if (gmA < R0)
                *reinterpret_cast<float2*>(d_g + (size_t)gmA * NC + c) =
                    make_float2(accG[j][0], accG[j][1]);
            if (gmB < R0)
                *reinterpret_cast<float2*>(d_g + (size_t)gmB * NC + c) =
                    make_float2(accG[j][2], accG[j][3]);
        }
        if (doY) {
#pragma unroll
            for (int j = 0; j < 8; j++) {
                int c = j * 8 + tig * 2;
                if (gmA < R1)
                    *reinterpret_cast<float2*>(d_yroot + (size_t)gmA * NC + c) =
                        make_float2(accY[j][0], accY[j][1]);
                if (gmB < R1)
                    *reinterpret_cast<float2*>(d_yroot + (size_t)gmB * NC + c) =
                        make_float2(accY[j][2], accY[j][3]);
            }
        }
    }
}

// ---------------- layer-2 edge-parallel aggregation of g --------------------
__global__ void agg2_kernel(const int* __restrict__ ea,
                            const int* __restrict__ eb, int E) {
    int gid  = blockIdx.x * blockDim.x + threadIdx.x;
    int e    = gid >> 5;
    int lane = gid & 31;
    if (e >= E) return;
    bool a_is_src = d_emax[2] >= d_emax[3];
    int s = a_is_src ? ea[e] : eb[e];
    int t = a_is_src ? eb[e] : ea[e];
    if ((unsigned)s >= R0 || (unsigned)t >= R1) return;
    float2 v = *reinterpret_cast<const float2*>(d_g + (size_t)s * NC + lane * 2);
    atomicAdd(&d_gsum[t * NC + lane * 2 + 0], v.x);
    atomicAdd(&d_gsum[t * NC + lane * 2 + 1], v.y);
    if (lane == 0) atomicAdd(&d_cnt1f[t], 1.0f);
}

// ---------------- final: logits = yroot + gsum/cnt + b2; log_softmax --------
__global__ void final_kernel(const float* __restrict__ b2, float* __restrict__ out) {
    int gid  = blockIdx.x * blockDim.x + threadIdx.x;
    int w    = gid >> 5;
    int lane = gid & 31;
    if (w >= R1) return;
    float inv = 1.f / fmaxf(d_cnt1f[w], 1.f);
    float vx = d_gsum[w * NC + lane * 2 + 0] * inv
             + d_yroot[w * NC + lane * 2 + 0] + b2[lane * 2 + 0];
    float vy = d_gsum[w * NC + lane * 2 + 1] * inv
             + d_yroot[w * NC + lane * 2 + 1] + b2[lane * 2 + 1];
    float m = fmaxf(vx, vy);
#pragma unroll
    for (int o = 16; o; o >>= 1) m = fmaxf(m, __shfl_xor_sync(0xffffffffu, m, o));
    float s = expf(vx - m) + expf(vy - m);
#pragma unroll
    for (int o = 16; o; o >>= 1) s += __shfl_xor_sync(0xffffffffu, s, o);
    float lse = logf(s);
    out[w * NC + lane * 2 + 0] = vx - m - lse;
    out[w * NC + lane * 2 + 1] = vy - m - lse;
}

// ---------------- launch ----------------------------------------------------
extern "C" void kernel_launch(void* const* d_in, const int* in_sizes, int n_in,
                              void* d_out, int out_size) {
    const float *x = 0, *W1r = 0, *W1n = 0, *b1 = 0, *W2r = 0, *W2n = 0, *b2 = 0;
    const int *eA0 = 0, *eB0 = 0, *eA1 = 0, *eB1 = 0;
    for (int i = 0; i < n_in; i++) {
        int sz = in_sizes[i];
        const void* p = d_in[i];
        if      (sz == NSRC * NF) { x = (const float*)p; }
        else if (sz == NF * NH)   { if (!W1r) W1r = (const float*)p; else W1n = (const float*)p; }
        else if (sz == NH)        { b1 = (const float*)p; }
        else if (sz == NH * NC)   { if (!W2r) W2r = (const float*)p; else W2n = (const float*)p; }
        else if (sz == NC)        { b2 = (const float*)p; }
        else if (sz == 1600000)   { if (!eA0) eA0 = (const int*)p; else eB0 = (const int*)p; }
        else if (sz == 500000)    { if (!eA1) eA1 = (const int*)p; else eB1 = (const int*)p; }
    }
    const int E0 = 1600000, E1 = 500000;
    float* out = (float*)d_out;
    (void)out_size;

    static int smem_set = 0;
    if (!smem_set) {
        cudaFuncSetAttribute(mma_fused_kernel,
                             cudaFuncAttributeMaxDynamicSharedMemorySize,
                             128 * APITCH * 2);
        smem_set = 1;
    }

    zero_kernel<<<(R0 * NF + 255) / 256, 256>>>();

    edgemax_kernel<<<256, 256>>>(eA0, eB0, E0, 0);
    edgemax_kernel<<<256, 256>>>(eA1, eB1, E1, 2);

    agg1_kernel<<<((size_t)E0 * 32 + 255) / 256, 256>>>(x, eA0, eB0, E0);
    norm1_kernel<<<(R0 * NF + 255) / 256, 256>>>();

    // bf16 operand prep
    convA_kernel<<<(int)(((size_t)MROWS * 256 + 255) / 256), 256>>>(x);
    convW1_kernel<<<(NHPAD * 256 + 255) / 256, 256>>>(W1r, W1n);
    convW2_kernel<<<(NC * NHPAD + 255) / 256, 256>>>(W2n, W2r);

    // fused tensor-core GEMM chain (HMMA; tcgen05 not available at compute_103)
    mma_fused_kernel<<<MTILES, 256, 128 * APITCH * 2>>>(b1);

    agg2_kernel<<<((size_t)E1 * 32 + 255) / 256, 256>>>(eA1, eB1, E1);

    final_kernel<<<(R1 * 32 + 255) / 256, 256>>>(b2, out);
}

// round 11
// speedup vs baseline: 2.7191x; 1.2827x over previous
#include <cuda_runtime.h>
#include <cuda_bf16.h>
#include <math.h>

// Problem constants (match reference setup_inputs)
#define NSRC   200000
#define NF     128
#define NH     1500
#define NC     64
#define R0     50000
#define R1     10000
#define NHPAD  1536
#define MTILES 391
#define MROWS  (MTILES * 128)   // 50048
#define NT     24               // N-slabs of 64 covering 1500 (padded to 1536)
#define E0C    1600000
#define E1C    500000
#define ZN     (R1 * NC)        // 640000: largest per-call-reset array

// ---------------- scratch (__device__ globals; no allocation allowed) --------
__device__ float d_g[R0 * NC];                // 12.8 MB
__device__ float d_yroot[R1 * NC];
__device__ float d_gsum[R1 * NC];
__device__ float d_cnt1f[R1];
__device__ int   d_emax[4];
__device__ int   d_cnt0[R0];
__device__ int   d_off0[R0 + 1];
__device__ int   d_cur0[R0];
__device__ int   d_csr0[E0C];
__device__ __nv_bfloat16 d_Ab[(size_t)MROWS * 256];   // 25.6 MB  [x | xmean] bf16
__device__ __nv_bfloat16 d_W1b[NHPAD * 256];          // [n][k] = W1{r,n}[k][n]
__device__ __nv_bfloat16 d_W2nb[NC * NHPAD];          // [c][n] = W2n[n][c]
__device__ __nv_bfloat16 d_W2rb[NC * NHPAD];          // [c][n] = W2r[n][c]

__device__ __forceinline__ unsigned pack_bf16(float lo, float hi) {
    unsigned r;
    asm("cvt.rn.bf16x2.f32 %0, %1, %2;" : "=r"(r) : "f"(hi), "f"(lo));
    return r;
}

// ---------------- zero accumulators (every call; graph replays) -------------
// NOTE: grid must cover ZN = R1*NC (largest reset array). R10 bug: grid only
// covered R0 threads, so d_gsum accumulated across graph replays.
__global__ void zero_kernel() {
    int i = blockIdx.x * blockDim.x + threadIdx.x;
    if (i < R1 * NC) d_gsum[i] = 0.f;
    if (i < R1)      d_cnt1f[i] = 0.f;
    if (i < R0)      d_cnt0[i] = 0;
    if (i < 4)       d_emax[i] = 0;
}

__global__ void edgemax_kernel(const int* __restrict__ a,
                               const int* __restrict__ b, int n, int slot) {
    __shared__ int sa, sb;
    if (threadIdx.x == 0) { sa = 0; sb = 0; }
    __syncthreads();
    int i = blockIdx.x * blockDim.x + threadIdx.x;
    int va = 0, vb = 0;
    for (; i < n; i += gridDim.x * blockDim.x) { va = max(va, a[i]); vb = max(vb, b[i]); }
    atomicMax(&sa, va);
    atomicMax(&sb, vb);
    __syncthreads();
    if (threadIdx.x == 0) { atomicMax(&d_emax[slot], sa); atomicMax(&d_emax[slot + 1], sb); }
}

// ---------------- CSR build for layer-1 edges -------------------------------
__global__ void hist0_kernel(const int* __restrict__ ea,
                             const int* __restrict__ eb, int E) {
    int i = blockIdx.x * blockDim.x + threadIdx.x;
    if (i >= E) return;
    bool a_is_src = d_emax[0] >= d_emax[1];
    int t = a_is_src ? eb[i] : ea[i];
    if ((unsigned)t < R0) atomicAdd(&d_cnt0[t], 1);
}

// single-block exclusive scan over d_cnt0 -> d_off0, d_cur0
__global__ void scan0_kernel() {
    __shared__ int buf[1024];
    __shared__ int carry;
    if (threadIdx.x == 0) carry = 0;
    __syncthreads();
    for (int base = 0; base < R0; base += 1024) {
        int i = base + threadIdx.x;
        int v = (i < R0) ? d_cnt0[i] : 0;
        buf[threadIdx.x] = v;
        __syncthreads();
        for (int s = 1; s < 1024; s <<= 1) {
            int t = (threadIdx.x >= s) ? buf[threadIdx.x - s] : 0;
            __syncthreads();
            buf[threadIdx.x] += t;
            __syncthreads();
        }
        if (i < R0) { int ex = carry + buf[threadIdx.x] - v; d_off0[i] = ex; d_cur0[i] = ex; }
        __syncthreads();
        if (threadIdx.x == 0) carry += buf[1023];
        __syncthreads();
    }
    if (threadIdx.x == 0) d_off0[R0] = carry;
}

__global__ void scatter0_kernel(const int* __restrict__ ea,
                                const int* __restrict__ eb, int E) {
    int i = blockIdx.x * blockDim.x + threadIdx.x;
    if (i >= E) return;
    bool a_is_src = d_emax[0] >= d_emax[1];
    int s = a_is_src ? ea[i] : eb[i];
    int t = a_is_src ? eb[i] : ea[i];
    if ((unsigned)t >= R0 || (unsigned)s >= NSRC) return;
    int p = atomicAdd(&d_cur0[t], 1);
    d_csr0[p] = s;
}

// ---------------- gather + mean + bf16 convert, writes d_Ab directly --------
// one warp per target row; lane covers 4 feature columns
__global__ void gather_conv_kernel(const float* __restrict__ x) {
    int w    = (blockIdx.x * blockDim.x + threadIdx.x) >> 5;
    int lane = threadIdx.x & 31;
    if (w >= R0) return;
    int beg = d_off0[w], end = d_off0[w + 1];
    float4 acc0 = make_float4(0.f, 0.f, 0.f, 0.f);
    float4 acc1 = make_float4(0.f, 0.f, 0.f, 0.f);
    int e = beg;
    for (; e + 1 < end; e += 2) {
        int s0 = d_csr0[e], s1 = d_csr0[e + 1];
        float4 v0 = *reinterpret_cast<const float4*>(x + (size_t)s0 * NF + lane * 4);
        float4 v1 = *reinterpret_cast<const float4*>(x + (size_t)s1 * NF + lane * 4);
        acc0.x += v0.x; acc0.y += v0.y; acc0.z += v0.z; acc0.w += v0.w;
        acc1.x += v1.x; acc1.y += v1.y; acc1.z += v1.z; acc1.w += v1.w;
    }
    if (e < end) {
        int s0 = d_csr0[e];
        float4 v0 = *reinterpret_cast<const float4*>(x + (size_t)s0 * NF + lane * 4);
        acc0.x += v0.x; acc0.y += v0.y; acc0.z += v0.z; acc0.w += v0.w;
    }
    float inv = 1.f / fmaxf((float)(end - beg), 1.f);
    unsigned m0 = pack_bf16((acc0.x + acc1.x) * inv, (acc0.y + acc1.y) * inv);
    unsigned m1 = pack_bf16((acc0.z + acc1.z) * inv, (acc0.w + acc1.w) * inv);
    __nv_bfloat16* row = d_Ab + (size_t)w * 256;
    *reinterpret_cast<uint2*>(row + 128 + lane * 4) = make_uint2(m0, m1);
    // root half: x[w] -> bf16
    float4 xv = *reinterpret_cast<const float4*>(x + (size_t)w * NF + lane * 4);
    *reinterpret_cast<uint2*>(row + lane * 4) =
        make_uint2(pack_bf16(xv.x, xv.y), pack_bf16(xv.z, xv.w));
}

// ---------------- bf16 weight preparation -----------------------------------
__global__ void convW1_kernel(const float* __restrict__ W1r, const float* __restrict__ W1n) {
    int i = blockIdx.x * blockDim.x + threadIdx.x;
    if (i >= NHPAD * 256) return;
    int n = i >> 8, k = i & 255;
    float v = 0.f;
    if (n < NH) v = (k < 128) ? W1r[(size_t)k * NH + n] : W1n[(size_t)(k - 128) * NH + n];
    d_W1b[i] = __float2bfloat16(v);
}
__global__ void convW2_kernel(const float* __restrict__ W2n, const float* __restrict__ W2r) {
    int i = blockIdx.x * blockDim.x + threadIdx.x;
    if (i >= NC * NHPAD) return;
    int c = i / NHPAD, n = i % NHPAD;
    float vn = 0.f, vr = 0.f;
    if (n < NH) { vn = W2n[(size_t)n * NC + c]; vr = W2r[(size_t)n * NC + c]; }
    d_W2nb[i] = __float2bfloat16(vn);
    d_W2rb[i] = __float2bfloat16(vr);
}

// ---------------- HMMA helpers ----------------------------------------------
__device__ __forceinline__ void mma16816(float* c, unsigned a0, unsigned a1,
                                         unsigned a2, unsigned a3,
                                         unsigned b0, unsigned b1) {
    asm volatile(
        "mma.sync.aligned.m16n8k16.row.col.f32.bf16.bf16.f32 "
        "{%0,%1,%2,%3}, {%4,%5,%6,%7}, {%8,%9}, {%0,%1,%2,%3};"
        : "+f"(c[0]), "+f"(c[1]), "+f"(c[2]), "+f"(c[3])
        : "r"(a0), "r"(a1), "r"(a2), "r"(a3), "r"(b0), "r"(b1));
}

// ---------------- fused GEMM chain on HMMA tensor cores ---------------------
#define APITCH 264   // bf16 units; 528B rows -> conflict-free frag loads

__global__ __launch_bounds__(256) void mma_fused_kernel(const float* __restrict__ b1) {
    extern __shared__ __nv_bfloat16 As[];   // [128][APITCH]
    int tid  = threadIdx.x;
    int warp = tid >> 5;
    int lane = tid & 31;
    int g    = lane >> 2;     // 0..7
    int tig  = lane & 3;      // 0..3
    int m0   = blockIdx.x * 128;
    int mrow = warp * 16;

    for (int idx = tid; idx < 128 * 32; idx += 256) {
        int row = idx >> 5, c8 = idx & 31;
        uint4 v = reinterpret_cast<const uint4*>(d_Ab + (size_t)(m0 + row) * 256)[c8];
        *reinterpret_cast<uint4*>(&As[row * APITCH + c8 * 8]) = v;
    }
    __syncthreads();

    float accG[8][4], accY[8][4];
#pragma unroll
    for (int j = 0; j < 8; j++)
#pragma unroll
        for (int q = 0; q < 4; q++) { accG[j][q] = 0.f; accY[j][q] = 0.f; }

    const bool doY = (m0 < R1);

    for (int it = 0; it < NT; it++) {
        int n0 = it * 64;
        float accH[8][4];
#pragma unroll
        for (int j = 0; j < 8; j++)
#pragma unroll
            for (int q = 0; q < 4; q++) accH[j][q] = 0.f;

#pragma unroll 4
        for (int kk = 0; kk < 16; kk++) {
            int kb = kk * 16;
            unsigned a0 = *reinterpret_cast<unsigned*>(&As[(mrow + g)     * APITCH + kb + tig * 2]);
            unsigned a1 = *reinterpret_cast<unsigned*>(&As[(mrow + g + 8) * APITCH + kb + tig * 2]);
            unsigned a2 = *reinterpret_cast<unsigned*>(&As[(mrow + g)     * APITCH + kb + 8 + tig * 2]);
            unsigned a3 = *reinterpret_cast<unsigned*>(&As[(mrow + g + 8) * APITCH + kb + 8 + tig * 2]);
#pragma unroll
            for (int j = 0; j < 8; j++) {
                const __nv_bfloat16* bp = d_W1b + (size_t)(n0 + j * 8 + g) * 256 + kb;
                unsigned b0 = *reinterpret_cast<const unsigned*>(bp + tig * 2);
                unsigned b1f = *reinterpret_cast<const unsigned*>(bp + 8 + tig * 2);
                mma16816(accH[j], a0, a1, a2, a3, b0, b1f);
            }
        }

        unsigned hfrag[4][4];
#pragma unroll
        for (int j = 0; j < 8; j++) {
            int c0 = n0 + j * 8 + tig * 2;
            float bb0 = (c0     < NH) ? __ldg(b1 + c0)     : 0.f;
            float bb1 = (c0 + 1 < NH) ? __ldg(b1 + c0 + 1) : 0.f;
            float h0 = (c0     < NH) ? fmaxf(accH[j][0] + bb0, 0.f) : 0.f;
            float h1 = (c0 + 1 < NH) ? fmaxf(accH[j][1] + bb1, 0.f) : 0.f;
            float h2 = (c0     < NH) ? fmaxf(accH[j][2] + bb0, 0.f) : 0.f;
            float h3 = (c0 + 1 < NH) ? fmaxf(accH[j][3] + bb1, 0.f) : 0.f;
            hfrag[j >> 1][(j & 1) * 2 + 0] = pack_bf16(h0, h1);
            hfrag[j >> 1][(j & 1) * 2 + 1] = pack_bf16(h2, h3);
        }

#pragma unroll
        for (int kk = 0; kk < 4; kk++) {
            int kb = n0 + kk * 16;
            unsigned a0 = hfrag[kk][0], a1 = hfrag[kk][1];
            unsigned a2 = hfrag[kk][2], a3 = hfrag[kk][3];
#pragma unroll
            for (int j = 0; j < 8; j++) {
                const __nv_bfloat16* bp = d_W2nb + (size_t)(j * 8 + g) * NHPAD + kb;
                unsigned b0 = *reinterpret_cast<const unsigned*>(bp + tig * 2);
                unsigned b1f = *reinterpret_cast<const unsigned*>(bp + 8 + tig * 2);
                mma16816(accG[j], a0, a1, a2, a3, b0, b1f);
            }
            if (doY) {
#pragma unroll
                for (int j = 0; j < 8; j++) {
                    const __nv_bfloat16* bp = d_W2rb + (size_t)(j * 8 + g) * NHPAD + kb;
                    unsigned b0 = *reinterpret_cast<const unsigned*>(bp + tig * 2);
                    unsigned b1f = *reinterpret_cast<const unsigned*>(bp + 8 + tig * 2);
                    mma16816(accY[j], a0, a1, a2, a3, b0, b1f);
                }
            }
        }
    }

    {
        int gmA = m0 + mrow + g;
        int gmB = gmA + 8;
#pragma unroll
        for (int j = 0; j < 8; j++) {
            int c = j * 8 + tig * 2;
            if (gmA < R0)
                *reinterpret_cast<float2*>(d_g + (size_t)gmA * NC + c) =
                    make_float2(accG[j][0], accG[j][1]);
            if (gmB < R0)
                *reinterpret_cast<float2*>(d_g + (size_t)gmB * NC + c) =
                    make_float2(accG[j][2], accG[j][3]);
        }
        if (doY) {
#pragma unroll
            for (int j = 0; j < 8; j++) {
                int c = j * 8 + tig * 2;
                if (gmA < R1)
                    *reinterpret_cast<float2*>(d_yroot + (size_t)gmA * NC + c) =
                        make_float2(accY[j][0], accY[j][1]);
                if (gmB < R1)
                    *reinterpret_cast<float2*>(d_yroot + (size_t)gmB * NC + c) =
                        make_float2(accY[j][2], accY[j][3]);
            }
        }
    }
}

// ---------------- layer-2 edge-parallel aggregation of g --------------------
__global__ void agg2_kernel(const int* __restrict__ ea,
                            const int* __restrict__ eb, int E) {
    int gid  = blockIdx.x * blockDim.x + threadIdx.x;
    int e    = gid >> 5;
    int lane = gid & 31;
    if (e >= E) return;
    bool a_is_src = d_emax[2] >= d_emax[3];
    int s = a_is_src ? ea[e] : eb[e];
    int t = a_is_src ? eb[e] : ea[e];
    if ((unsigned)s >= R0 || (unsigned)t >= R1) return;
    float2 v = *reinterpret_cast<const float2*>(d_g + (size_t)s * NC + lane * 2);
    atomicAdd(&d_gsum[t * NC + lane * 2 + 0], v.x);
    atomicAdd(&d_gsum[t * NC + lane * 2 + 1], v.y);
    if (lane == 0) atomicAdd(&d_cnt1f[t], 1.0f);
}

// ---------------- final: logits = yroot + gsum/cnt + b2; log_softmax --------
__global__ void final_kernel(const float* __restrict__ b2, float* __restrict__ out) {
    int gid  = blockIdx.x * blockDim.x + threadIdx.x;
    int w    = gid >> 5;
    int lane = gid & 31;
    if (w >= R1) return;
    float inv = 1.f / fmaxf(d_cnt1f[w], 1.f);
    float vx = d_gsum[w * NC + lane * 2 + 0] * inv
             + d_yroot[w * NC + lane * 2 + 0] + b2[lane * 2 + 0];
    float vy = d_gsum[w * NC + lane * 2 + 1] * inv
             + d_yroot[w * NC + lane * 2 + 1] + b2[lane * 2 + 1];
    float m = fmaxf(vx, vy);
#pragma unroll
    for (int o = 16; o; o >>= 1) m = fmaxf(m, __shfl_xor_sync(0xffffffffu, m, o));
    float s = expf(vx - m) + expf(vy - m);
#pragma unroll
    for (int o = 16; o; o >>= 1) s += __shfl_xor_sync(0xffffffffu, s, o);
    float lse = logf(s);
    out[w * NC + lane * 2 + 0] = vx - m - lse;
    out[w * NC + lane * 2 + 1] = vy - m - lse;
}

// ---------------- launch ----------------------------------------------------
extern "C" void kernel_launch(void* const* d_in, const int* in_sizes, int n_in,
                              void* d_out, int out_size) {
    const float *x = 0, *W1r = 0, *W1n = 0, *b1 = 0, *W2r = 0, *W2n = 0, *b2 = 0;
    const int *eA0 = 0, *eB0 = 0, *eA1 = 0, *eB1 = 0;
    for (int i = 0; i < n_in; i++) {
        int sz = in_sizes[i];
        const void* p = d_in[i];
        if      (sz == NSRC * NF) { x = (const float*)p; }
        else if (sz == NF * NH)   { if (!W1r) W1r = (const float*)p; else W1n = (const float*)p; }
        else if (sz == NH)        { b1 = (const float*)p; }
        else if (sz == NH * NC)   { if (!W2r) W2r = (const float*)p; else W2n = (const float*)p; }
        else if (sz == NC)        { b2 = (const float*)p; }
        else if (sz == E0C)       { if (!eA0) eA0 = (const int*)p; else eB0 = (const int*)p; }
        else if (sz == E1C)       { if (!eA1) eA1 = (const int*)p; else eB1 = (const int*)p; }
    }
    const int E0 = E0C, E1 = E1C;
    float* out = (float*)d_out;
    (void)out_size;

    static int smem_set = 0;
    if (!smem_set) {
        cudaFuncSetAttribute(mma_fused_kernel,
                             cudaFuncAttributeMaxDynamicSharedMemorySize,
                             128 * APITCH * 2);
        smem_set = 1;
    }

    // FULL coverage of all per-call-reset arrays (R10 bug: grid too small)
    zero_kernel<<<(ZN + 255) / 256, 256>>>();

    edgemax_kernel<<<256, 256>>>(eA0, eB0, E0, 0);
    edgemax_kernel<<<256, 256>>>(eA1, eB1, E1, 2);

    // CSR build for layer-1 edges
    hist0_kernel<<<(E0 + 255) / 256, 256>>>(eA0, eB0, E0);
    scan0_kernel<<<1, 1024>>>();
    scatter0_kernel<<<(E0 + 255) / 256, 256>>>(eA0, eB0, E0);

    // gather + mean + bf16 conversion straight into d_Ab (replaces agg1+norm1+convA)
    gather_conv_kernel<<<(R0 * 32 + 255) / 256, 256>>>(x);

    // bf16 weight prep
    convW1_kernel<<<(NHPAD * 256 + 255) / 256, 256>>>(W1r, W1n);
    convW2_kernel<<<(NC * NHPAD + 255) / 256, 256>>>(W2n, W2r);

    // fused tensor-core GEMM chain
    mma_fused_kernel<<<MTILES, 256, 128 * APITCH * 2>>>(b1);

    agg2_kernel<<<((size_t)E1 * 32 + 255) / 256, 256>>>(eA1, eB1, E1);

    final_kernel<<<(R1 * 32 + 255) / 256, 256>>>(b2, out);
}

// round 12
// speedup vs baseline: 5.9464x; 2.1869x over previous
#include <cuda_runtime.h>
#include <cuda_bf16.h>
#include <math.h>

// Problem constants (match reference setup_inputs)
#define NSRC   200000
#define NF     128
#define NH     1500
#define NC     64
#define R0     50000
#define R1     10000
#define NHPAD  1536
#define MTILES 391
#define MROWS  (MTILES * 128)   // 50048
#define NT     24               // N-slabs of 64 covering 1500 (padded to 1536)
#define E0C    1600000
#define E1C    500000
#define ZN     (R1 * NC)        // 640000: largest per-call-reset array

// ---------------- scratch (__device__ globals; no allocation allowed) --------
__device__ float d_g[R0 * NC];                // 12.8 MB
__device__ float d_yroot[R1 * NC];
__device__ float d_gsum[R1 * NC];
__device__ float d_cnt1f[R1];
__device__ int   d_emax[4];
__device__ int   d_cnt0[R0];
__device__ int   d_off0[R0 + 1];
__device__ int   d_cur0[R0];
__device__ int   d_csr0[E0C];
__device__ __nv_bfloat16 d_Ab[(size_t)MROWS * 256];   // 25.6 MB  [x | xmean] bf16
__device__ __nv_bfloat16 d_W1b[NHPAD * 256];          // [n][k] = W1{r,n}[k][n]
__device__ __nv_bfloat16 d_W2nb[NC * NHPAD];          // [c][n] = W2n[n][c]
__device__ __nv_bfloat16 d_W2rb[NC * NHPAD];          // [c][n] = W2r[n][c]

__device__ __forceinline__ unsigned pack_bf16(float lo, float hi) {
    unsigned r;
    asm("cvt.rn.bf16x2.f32 %0, %1, %2;" : "=r"(r) : "f"(hi), "f"(lo));
    return r;
}

// ---------------- zero accumulators (every call; graph replays) -------------
__global__ void zero_kernel() {
    int i = blockIdx.x * blockDim.x + threadIdx.x;
    if (i < R1 * NC) d_gsum[i] = 0.f;
    if (i < R1)      d_cnt1f[i] = 0.f;
    if (i < R0)      d_cnt0[i] = 0;
    if (i < 4)       d_emax[i] = 0;
}

__global__ void edgemax_kernel(const int* __restrict__ a,
                               const int* __restrict__ b, int n, int slot) {
    __shared__ int sa, sb;
    if (threadIdx.x == 0) { sa = 0; sb = 0; }
    __syncthreads();
    int i = blockIdx.x * blockDim.x + threadIdx.x;
    int va = 0, vb = 0;
    for (; i < n; i += gridDim.x * blockDim.x) { va = max(va, a[i]); vb = max(vb, b[i]); }
    atomicMax(&sa, va);
    atomicMax(&sb, vb);
    __syncthreads();
    if (threadIdx.x == 0) { atomicMax(&d_emax[slot], sa); atomicMax(&d_emax[slot + 1], sb); }
}

// ---------------- CSR build for layer-1 edges -------------------------------
__global__ void hist0_kernel(const int* __restrict__ ea,
                             const int* __restrict__ eb, int E) {
    int i = blockIdx.x * blockDim.x + threadIdx.x;
    if (i >= E) return;
    bool a_is_src = d_emax[0] >= d_emax[1];
    int t = a_is_src ? eb[i] : ea[i];
    if ((unsigned)t < R0) atomicAdd(&d_cnt0[t], 1);
}

// single-block exclusive scan over d_cnt0 -> d_off0, d_cur0
__global__ void scan0_kernel() {
    __shared__ int buf[1024];
    __shared__ int carry;
    if (threadIdx.x == 0) carry = 0;
    __syncthreads();
    for (int base = 0; base < R0; base += 1024) {
        int i = base + threadIdx.x;
        int v = (i < R0) ? d_cnt0[i] : 0;
        buf[threadIdx.x] = v;
        __syncthreads();
        for (int s = 1; s < 1024; s <<= 1) {
            int t = (threadIdx.x >= s) ? buf[threadIdx.x - s] : 0;
            __syncthreads();
            buf[threadIdx.x] += t;
            __syncthreads();
        }
        if (i < R0) { int ex = carry + buf[threadIdx.x] - v; d_off0[i] = ex; d_cur0[i] = ex; }
        __syncthreads();
        if (threadIdx.x == 0) carry += buf[1023];
        __syncthreads();
    }
    if (threadIdx.x == 0) d_off0[R0] = carry;
}

__global__ void scatter0_kernel(const int* __restrict__ ea,
                                const int* __restrict__ eb, int E) {
    int i = blockIdx.x * blockDim.x + threadIdx.x;
    if (i >= E) return;
    bool a_is_src = d_emax[0] >= d_emax[1];
    int s = a_is_src ? ea[i] : eb[i];
    int t = a_is_src ? eb[i] : ea[i];
    if ((unsigned)t >= R0 || (unsigned)s >= NSRC) return;
    int p = atomicAdd(&d_cur0[t], 1);
    d_csr0[p] = s;
}

// ---------------- gather + mean + bf16 convert, writes d_Ab directly --------
__global__ void gather_conv_kernel(const float* __restrict__ x) {
    int w    = (blockIdx.x * blockDim.x + threadIdx.x) >> 5;
    int lane = threadIdx.x & 31;
    if (w >= R0) return;
    int beg = d_off0[w], end = d_off0[w + 1];
    float4 acc0 = make_float4(0.f, 0.f, 0.f, 0.f);
    float4 acc1 = make_float4(0.f, 0.f, 0.f, 0.f);
    int e = beg;
    for (; e + 1 < end; e += 2) {
        int s0 = d_csr0[e], s1 = d_csr0[e + 1];
        float4 v0 = *reinterpret_cast<const float4*>(x + (size_t)s0 * NF + lane * 4);
        float4 v1 = *reinterpret_cast<const float4*>(x + (size_t)s1 * NF + lane * 4);
        acc0.x += v0.x; acc0.y += v0.y; acc0.z += v0.z; acc0.w += v0.w;
        acc1.x += v1.x; acc1.y += v1.y; acc1.z += v1.z; acc1.w += v1.w;
    }
    if (e < end) {
        int s0 = d_csr0[e];
        float4 v0 = *reinterpret_cast<const float4*>(x + (size_t)s0 * NF + lane * 4);
        acc0.x += v0.x; acc0.y += v0.y; acc0.z += v0.z; acc0.w += v0.w;
    }
    float inv = 1.f / fmaxf((float)(end - beg), 1.f);
    unsigned m0 = pack_bf16((acc0.x + acc1.x) * inv, (acc0.y + acc1.y) * inv);
    unsigned m1 = pack_bf16((acc0.z + acc1.z) * inv, (acc0.w + acc1.w) * inv);
    __nv_bfloat16* row = d_Ab + (size_t)w * 256;
    *reinterpret_cast<uint2*>(row + 128 + lane * 4) = make_uint2(m0, m1);
    float4 xv = *reinterpret_cast<const float4*>(x + (size_t)w * NF + lane * 4);
    *reinterpret_cast<uint2*>(row + lane * 4) =
        make_uint2(pack_bf16(xv.x, xv.y), pack_bf16(xv.z, xv.w));
}

// ---------------- bf16 weight preparation -----------------------------------
__global__ void convW1_kernel(const float* __restrict__ W1r, const float* __restrict__ W1n) {
    int i = blockIdx.x * blockDim.x + threadIdx.x;
    if (i >= NHPAD * 256) return;
    int n = i >> 8, k = i & 255;
    float v = 0.f;
    if (n < NH) v = (k < 128) ? W1r[(size_t)k * NH + n] : W1n[(size_t)(k - 128) * NH + n];
    d_W1b[i] = __float2bfloat16(v);
}
__global__ void convW2_kernel(const float* __restrict__ W2n, const float* __restrict__ W2r) {
    int i = blockIdx.x * blockDim.x + threadIdx.x;
    if (i >= NC * NHPAD) return;
    int c = i / NHPAD, n = i % NHPAD;
    float vn = 0.f, vr = 0.f;
    if (n < NH) { vn = W2n[(size_t)n * NC + c]; vr = W2r[(size_t)n * NC + c]; }
    d_W2nb[i] = __float2bfloat16(vn);
    d_W2rb[i] = __float2bfloat16(vr);
}

// ---------------- HMMA helpers ----------------------------------------------
__device__ __forceinline__ void mma16816(float* c, unsigned a0, unsigned a1,
                                         unsigned a2, unsigned a3,
                                         unsigned b0, unsigned b1) {
    asm volatile(
        "mma.sync.aligned.m16n8k16.row.col.f32.bf16.bf16.f32 "
        "{%0,%1,%2,%3}, {%4,%5,%6,%7}, {%8,%9}, {%0,%1,%2,%3};"
        : "+f"(c[0]), "+f"(c[1]), "+f"(c[2]), "+f"(c[3])
        : "r"(a0), "r"(a1), "r"(a2), "r"(a3), "r"(b0), "r"(b1));
}
__device__ __forceinline__ void ldsm_x4(unsigned& r0, unsigned& r1,
                                        unsigned& r2, unsigned& r3, unsigned addr) {
    asm volatile("ldmatrix.sync.aligned.m8n8.x4.shared.b16 {%0,%1,%2,%3}, [%4];"
                 : "=r"(r0), "=r"(r1), "=r"(r2), "=r"(r3) : "r"(addr));
}

// ---------------- fused GEMM chain on HMMA tensor cores ---------------------
// SMEM-staged operands + ldmatrix fragment delivery.
// Pitches: row stride must be ≡ 4 banks (16B) mod 32 banks for conflict-free
// 8-row ldmatrix phases: 264*2=528B=132w (132%32=4) ✓; 72*2=144B=36w (36%32=4) ✓
#define APITCH 264
#define BPITCH 264
#define WPITCH 72
#define SM_AS  0
#define SM_BS  (128 * APITCH)                  // bf16 units
#define SM_WS  (SM_BS + 64 * BPITCH)
#define SM_TOT ((SM_WS + 64 * WPITCH) * 2)     // bytes = 110592

__global__ __launch_bounds__(256, 2) void mma_fused_kernel(const float* __restrict__ b1) {
    extern __shared__ __nv_bfloat16 sm[];
    __nv_bfloat16* As = sm + SM_AS;
    __nv_bfloat16* Bs = sm + SM_BS;
    __nv_bfloat16* Ws = sm + SM_WS;
    int tid  = threadIdx.x;
    int warp = tid >> 5;
    int lane = tid & 31;
    int g    = lane >> 2;     // 0..7
    int tig  = lane & 3;      // 0..3
    int m0   = blockIdx.x * 128;
    int mrow = warp * 16;

    // stage A tile (128 x 256 bf16)
    for (int idx = tid; idx < 128 * 32; idx += 256) {
        int row = idx >> 5, c8 = idx & 31;
        uint4 v = reinterpret_cast<const uint4*>(d_Ab + (size_t)(m0 + row) * 256)[c8];
        *reinterpret_cast<uint4*>(&As[row * APITCH + c8 * 8]) = v;
    }

    // per-lane ldmatrix base addresses (byte offsets into shared space)
    unsigned saA = (unsigned)__cvta_generic_to_shared(As);
    unsigned saB = (unsigned)__cvta_generic_to_shared(Bs);
    unsigned saW = (unsigned)__cvta_generic_to_shared(Ws);
    // A: lanes 0-15 -> rows mrow+(lane&15) at col 0; lanes 16-31 same rows col+8
    unsigned aBase = saA + ((mrow + (lane & 15)) * APITCH + (lane >> 4) * 8) * 2;
    // B/W: 4 matrices per x4 = j-pair {b0,b1} x 2; n = jp*16 + bit4*8 + (lane&7),
    // col = bit3*8
    unsigned bBase[4], wBase[4];
#pragma unroll
    for (int jp = 0; jp < 4; jp++) {
        int n   = jp * 16 + ((lane >> 4) & 1) * 8 + (lane & 7);
        int col = ((lane >> 3) & 1) * 8;
        bBase[jp] = saB + (n * BPITCH + col) * 2;
        wBase[jp] = saW + (n * WPITCH + col) * 2;
    }

    float accG[8][4], accY[8][4];
#pragma unroll
    for (int j = 0; j < 8; j++)
#pragma unroll
        for (int q = 0; q < 4; q++) { accG[j][q] = 0.f; accY[j][q] = 0.f; }

    const bool doY = (m0 < R1);

    for (int it = 0; it < NT; it++) {
        int n0 = it * 64;
        __syncthreads();   // previous slab fully consumed (and A staged on it=0)
        // stage W1 slab: 64 rows x 256 bf16
        for (int idx = tid; idx < 64 * 32; idx += 256) {
            int row = idx >> 5, c8 = idx & 31;
            uint4 v = reinterpret_cast<const uint4*>(d_W1b + (size_t)(n0 + row) * 256)[c8];
            *reinterpret_cast<uint4*>(&Bs[row * BPITCH + c8 * 8]) = v;
        }
        // stage W2n slab: 64 rows(c) x 64 bf16(k)
        for (int idx = tid; idx < 64 * 8; idx += 256) {
            int row = idx >> 3, c8 = idx & 7;
            uint4 v = *reinterpret_cast<const uint4*>(d_W2nb + (size_t)row * NHPAD + n0 + c8 * 8);
            *reinterpret_cast<uint4*>(&Ws[row * WPITCH + c8 * 8]) = v;
        }
        __syncthreads();

        float accH[8][4];
#pragma unroll
        for (int j = 0; j < 8; j++)
#pragma unroll
            for (int q = 0; q < 4; q++) accH[j][q] = 0.f;

        // ---- MMA1: K=256 in 16 steps; A + B frags via ldmatrix.x4 ----
#pragma unroll 4
        for (int kk = 0; kk < 16; kk++) {
            unsigned a0, a1, a2, a3;
            ldsm_x4(a0, a1, a2, a3, aBase + kk * 32);
#pragma unroll
            for (int jp = 0; jp < 4; jp++) {
                unsigned r0, r1, r2, r3;
                ldsm_x4(r0, r1, r2, r3, bBase[jp] + kk * 32);
                mma16816(accH[jp * 2 + 0], a0, a1, a2, a3, r0, r1);
                mma16816(accH[jp * 2 + 1], a0, a1, a2, a3, r2, r3);
            }
        }

        // ---- bias + relu -> bf16 A-frags (register-only) ----
        unsigned hfrag[4][4];
#pragma unroll
        for (int j = 0; j < 8; j++) {
            int c0 = n0 + j * 8 + tig * 2;
            float bb0 = (c0     < NH) ? __ldg(b1 + c0)     : 0.f;
            float bb1 = (c0 + 1 < NH) ? __ldg(b1 + c0 + 1) : 0.f;
            float h0 = (c0     < NH) ? fmaxf(accH[j][0] + bb0, 0.f) : 0.f;
            float h1 = (c0 + 1 < NH) ? fmaxf(accH[j][1] + bb1, 0.f) : 0.f;
            float h2 = (c0     < NH) ? fmaxf(accH[j][2] + bb0, 0.f) : 0.f;
            float h3 = (c0 + 1 < NH) ? fmaxf(accH[j][3] + bb1, 0.f) : 0.f;
            hfrag[j >> 1][(j & 1) * 2 + 0] = pack_bf16(h0, h1);
            hfrag[j >> 1][(j & 1) * 2 + 1] = pack_bf16(h2, h3);
        }

        // ---- MMA2: accG += H @ W2n_slab (SMEM+ldmatrix) ----
#pragma unroll
        for (int kk = 0; kk < 4; kk++) {
            unsigned a0 = hfrag[kk][0], a1 = hfrag[kk][1];
            unsigned a2 = hfrag[kk][2], a3 = hfrag[kk][3];
#pragma unroll
            for (int jp = 0; jp < 4; jp++) {
                unsigned r0, r1, r2, r3;
                ldsm_x4(r0, r1, r2, r3, wBase[jp] + kk * 32);
                mma16816(accG[jp * 2 + 0], a0, a1, a2, a3, r0, r1);
                mma16816(accG[jp * 2 + 1], a0, a1, a2, a3, r2, r3);
            }
        }
        // ---- MMA3 (doY CTAs only, 79/391): scalar-LDG path as before ----
        if (doY) {
#pragma unroll
            for (int kk = 0; kk < 4; kk++) {
                int kb = n0 + kk * 16;
                unsigned a0 = hfrag[kk][0], a1 = hfrag[kk][1];
                unsigned a2 = hfrag[kk][2], a3 = hfrag[kk][3];
#pragma unroll
                for (int j = 0; j < 8; j++) {
                    const __nv_bfloat16* bp = d_W2rb + (size_t)(j * 8 + g) * NHPAD + kb;
                    unsigned b0 = *reinterpret_cast<const unsigned*>(bp + tig * 2);
                    unsigned b1f = *reinterpret_cast<const unsigned*>(bp + 8 + tig * 2);
                    mma16816(accY[j], a0, a1, a2, a3, b0, b1f);
                }
            }
        }
    }

    {
        int gmA = m0 + mrow + g;
        int gmB = gmA + 8;
#pragma unroll
        for (int j = 0; j < 8; j++) {
            int c = j * 8 + tig * 2;
            if (gmA < R0)
                *reinterpret_cast<float2*>(d_g + (size_t)gmA * NC + c) =
                    make_float2(accG[j][0], accG[j][1]);
            if (gmB < R0)
                *reinterpret_cast<float2*>(d_g + (size_t)gmB * NC + c) =
                    make_float2(accG[j][2], accG[j][3]);
        }
        if (doY) {
#pragma unroll
            for (int j = 0; j < 8; j++) {
                int c = j * 8 + tig * 2;
                if (gmA < R1)
                    *reinterpret_cast<float2*>(d_yroot + (size_t)gmA * NC + c) =
                        make_float2(accY[j][0], accY[j][1]);
                if (gmB < R1)
                    *reinterpret_cast<float2*>(d_yroot + (size_t)gmB * NC + c) =
                        make_float2(accY[j][2], accY[j][3]);
            }
        }
    }
}

// ---------------- layer-2 edge-parallel aggregation of g --------------------
__global__ void agg2_kernel(const int* __restrict__ ea,
                            const int* __restrict__ eb, int E) {
    int gid  = blockIdx.x * blockDim.x + threadIdx.x;
    int e    = gid >> 5;
    int lane = gid & 31;
    if (e >= E) return;
    bool a_is_src = d_emax[2] >= d_emax[3];
    int s = a_is_src ? ea[e] : eb[e];
    int t = a_is_src ? eb[e] : ea[e];
    if ((unsigned)s >= R0 || (unsigned)t >= R1) return;
    float2 v = *reinterpret_cast<const float2*>(d_g + (size_t)s * NC + lane * 2);
    atomicAdd(&d_gsum[t * NC + lane * 2 + 0], v.x);
    atomicAdd(&d_gsum[t * NC + lane * 2 + 1], v.y);
    if (lane == 0) atomicAdd(&d_cnt1f[t], 1.0f);
}

// ---------------- final: logits = yroot + gsum/cnt + b2; log_softmax --------
__global__ void final_kernel(const float* __restrict__ b2, float* __restrict__ out) {
    int gid  = blockIdx.x * blockDim.x + threadIdx.x;
    int w    = gid >> 5;
    int lane = gid & 31;
    if (w >= R1) return;
    float inv = 1.f / fmaxf(d_cnt1f[w], 1.f);
    float vx = d_gsum[w * NC + lane * 2 + 0] * inv
             + d_yroot[w * NC + lane * 2 + 0] + b2[lane * 2 + 0];
    float vy = d_gsum[w * NC + lane * 2 + 1] * inv
             + d_yroot[w * NC + lane * 2 + 1] + b2[lane * 2 + 1];
    float m = fmaxf(vx, vy);
#pragma unroll
    for (int o = 16; o; o >>= 1) m = fmaxf(m, __shfl_xor_sync(0xffffffffu, m, o));
    float s = expf(vx - m) + expf(vy - m);
#pragma unroll
    for (int o = 16; o; o >>= 1) s += __shfl_xor_sync(0xffffffffu, s, o);
    float lse = logf(s);
    out[w * NC + lane * 2 + 0] = vx - m - lse;
    out[w * NC + lane * 2 + 1] = vy - m - lse;
}

// ---------------- launch ----------------------------------------------------
extern "C" void kernel_launch(void* const* d_in, const int* in_sizes, int n_in,
                              void* d_out, int out_size) {
    const float *x = 0, *W1r = 0, *W1n = 0, *b1 = 0, *W2r = 0, *W2n = 0, *b2 = 0;
    const int *eA0 = 0, *eB0 = 0, *eA1 = 0, *eB1 = 0;
    for (int i = 0; i < n_in; i++) {
        int sz = in_sizes[i];
        const void* p = d_in[i];
        if      (sz == NSRC * NF) { x = (const float*)p; }
        else if (sz == NF * NH)   { if (!W1r) W1r = (const float*)p; else W1n = (const float*)p; }
        else if (sz == NH)        { b1 = (const float*)p; }
        else if (sz == NH * NC)   { if (!W2r) W2r = (const float*)p; else W2n = (const float*)p; }
        else if (sz == NC)        { b2 = (const float*)p; }
        else if (sz == E0C)       { if (!eA0) eA0 = (const int*)p; else eB0 = (const int*)p; }
        else if (sz == E1C)       { if (!eA1) eA1 = (const int*)p; else eB1 = (const int*)p; }
    }
    const int E0 = E0C, E1 = E1C;
    float* out = (float*)d_out;
    (void)out_size;

    static int smem_set = 0;
    if (!smem_set) {
        cudaFuncSetAttribute(mma_fused_kernel,
                             cudaFuncAttributeMaxDynamicSharedMemorySize, SM_TOT);
        smem_set = 1;
    }

    zero_kernel<<<(ZN + 255) / 256, 256>>>();

    edgemax_kernel<<<256, 256>>>(eA0, eB0, E0, 0);
    edgemax_kernel<<<256, 256>>>(eA1, eB1, E1, 2);

    // CSR build for layer-1 edges
    hist0_kernel<<<(E0 + 255) / 256, 256>>>(eA0, eB0, E0);
    scan0_kernel<<<1, 1024>>>();
    scatter0_kernel<<<(E0 + 255) / 256, 256>>>(eA0, eB0, E0);

    // gather + mean + bf16 conversion straight into d_Ab
    gather_conv_kernel<<<(R0 * 32 + 255) / 256, 256>>>(x);

    // bf16 weight prep
    convW1_kernel<<<(NHPAD * 256 + 255) / 256, 256>>>(W1r, W1n);
    convW2_kernel<<<(NC * NHPAD + 255) / 256, 256>>>(W2n, W2r);

    // fused tensor-core GEMM chain (SMEM-staged + ldmatrix fragment delivery)
    mma_fused_kernel<<<MTILES, 256, SM_TOT>>>(b1);

    agg2_kernel<<<((size_t)E1 * 32 + 255) / 256, 256>>>(eA1, eB1, E1);

    final_kernel<<<(R1 * 32 + 255) / 256, 256>>>(b2, out);
}

// round 13
// speedup vs baseline: 6.1328x; 1.0313x over previous
#include <cuda_runtime.h>
#include <cuda_bf16.h>
#include <math.h>

// Problem constants (match reference setup_inputs)
#define NSRC   200000
#define NF     128
#define NH     1500
#define NC     64
#define R0     50000
#define R1     10000
#define NHPAD  1536
#define MTILES 391
#define MROWS  (MTILES * 128)   // 50048
#define NT     24               // N-slabs of 64 covering 1500 (padded to 1536)
#define E0C    1600000
#define E1C    500000

// ---------------- scratch (__device__ globals; no allocation allowed) --------
__device__ float d_g[R0 * NC];                // 12.8 MB
__device__ float d_yroot[R1 * NC];
__device__ int   d_emax[4];
__device__ int   d_cnt0[R0];
__device__ int   d_off0[R0 + 1];
__device__ int   d_cur0[R0];
__device__ int   d_csr0[E0C];
__device__ int   d_cnt1[R1];
__device__ int   d_off1[R1 + 1];
__device__ int   d_cur1[R1];
__device__ int   d_csr1[E1C];
__device__ __nv_bfloat16 d_xb[(size_t)NSRC * NF];     // 51.2 MB  x in bf16
__device__ __nv_bfloat16 d_Ab[(size_t)MROWS * 256];   // 25.6 MB  [x | xmean] bf16
__device__ __nv_bfloat16 d_W1b[NHPAD * 256];          // [n][k] = W1{r,n}[k][n]
__device__ __nv_bfloat16 d_W2nb[NC * NHPAD];          // [c][n] = W2n[n][c]
__device__ __nv_bfloat16 d_W2rb[NC * NHPAD];          // [c][n] = W2r[n][c]

__device__ __forceinline__ unsigned pack_bf16(float lo, float hi) {
    unsigned r;
    asm("cvt.rn.bf16x2.f32 %0, %1, %2;" : "=r"(r) : "f"(hi), "f"(lo));
    return r;
}

// ---------------- zero per-call-reset state (graph replays) -----------------
// Largest reset array: d_cnt0 (R0). All reset arrays listed here — audit!
__global__ void zero_kernel() {
    int i = blockIdx.x * blockDim.x + threadIdx.x;
    if (i < R0) d_cnt0[i] = 0;
    if (i < R1) d_cnt1[i] = 0;
    if (i < 4)  d_emax[i] = 0;
}

__global__ void edgemax_kernel(const int* __restrict__ a,
                               const int* __restrict__ b, int n, int slot) {
    __shared__ int sa, sb;
    if (threadIdx.x == 0) { sa = 0; sb = 0; }
    __syncthreads();
    int i = blockIdx.x * blockDim.x + threadIdx.x;
    int va = 0, vb = 0;
    for (; i < n; i += gridDim.x * blockDim.x) { va = max(va, a[i]); vb = max(vb, b[i]); }
    atomicMax(&sa, va);
    atomicMax(&sb, vb);
    __syncthreads();
    if (threadIdx.x == 0) { atomicMax(&d_emax[slot], sa); atomicMax(&d_emax[slot + 1], sb); }
}

// ---------------- CSR build: layer-1 (slotbase 0) and layer-2 (slotbase 2) --
__global__ void hist0_kernel(const int* __restrict__ ea,
                             const int* __restrict__ eb, int E) {
    int i = blockIdx.x * blockDim.x + threadIdx.x;
    if (i >= E) return;
    bool a_is_src = d_emax[0] >= d_emax[1];
    int t = a_is_src ? eb[i] : ea[i];
    if ((unsigned)t < R0) atomicAdd(&d_cnt0[t], 1);
}
__global__ void hist1_kernel(const int* __restrict__ ea,
                             const int* __restrict__ eb, int E) {
    int i = blockIdx.x * blockDim.x + threadIdx.x;
    if (i >= E) return;
    bool a_is_src = d_emax[2] >= d_emax[3];
    int t = a_is_src ? eb[i] : ea[i];
    if ((unsigned)t < R1) atomicAdd(&d_cnt1[t], 1);
}

// single-block exclusive scan: which=0 -> cnt0/off0/cur0 (R0), which=1 -> R1
__global__ void scan_kernel(int which) {
    const int* cnt = which ? d_cnt1 : d_cnt0;
    int* off = which ? d_off1 : d_off0;
    int* cur = which ? d_cur1 : d_cur0;
    int n    = which ? R1 : R0;
    __shared__ int buf[1024];
    __shared__ int carry;
    if (threadIdx.x == 0) carry = 0;
    __syncthreads();
    for (int base = 0; base < n; base += 1024) {
        int i = base + threadIdx.x;
        int v = (i < n) ? cnt[i] : 0;
        buf[threadIdx.x] = v;
        __syncthreads();
        for (int s = 1; s < 1024; s <<= 1) {
            int t = (threadIdx.x >= s) ? buf[threadIdx.x - s] : 0;
            __syncthreads();
            buf[threadIdx.x] += t;
            __syncthreads();
        }
        if (i < n) { int ex = carry + buf[threadIdx.x] - v; off[i] = ex; cur[i] = ex; }
        __syncthreads();
        if (threadIdx.x == 0) carry += buf[1023];
        __syncthreads();
    }
    if (threadIdx.x == 0) off[n] = carry;
}

__global__ void scatter0_kernel(const int* __restrict__ ea,
                                const int* __restrict__ eb, int E) {
    int i = blockIdx.x * blockDim.x + threadIdx.x;
    if (i >= E) return;
    bool a_is_src = d_emax[0] >= d_emax[1];
    int s = a_is_src ? ea[i] : eb[i];
    int t = a_is_src ? eb[i] : ea[i];
    if ((unsigned)t >= R0 || (unsigned)s >= NSRC) return;
    int p = atomicAdd(&d_cur0[t], 1);
    d_csr0[p] = s;
}
__global__ void scatter1_kernel(const int* __restrict__ ea,
                                const int* __restrict__ eb, int E) {
    int i = blockIdx.x * blockDim.x + threadIdx.x;
    if (i >= E) return;
    bool a_is_src = d_emax[2] >= d_emax[3];
    int s = a_is_src ? ea[i] : eb[i];
    int t = a_is_src ? eb[i] : ea[i];
    if ((unsigned)t >= R1 || (unsigned)s >= R0) return;
    int p = atomicAdd(&d_cur1[t], 1);
    d_csr1[p] = s;
}

// ---------------- x -> bf16 (one pass; halves gather traffic) ---------------
__global__ void convX_kernel(const float* __restrict__ x) {
    size_t i = (size_t)blockIdx.x * blockDim.x + threadIdx.x;   // one per 4 elems
    if (i >= (size_t)NSRC * NF / 4) return;
    float4 v = reinterpret_cast<const float4*>(x)[i];
    reinterpret_cast<uint2*>(d_xb)[i] =
        make_uint2(pack_bf16(v.x, v.y), pack_bf16(v.z, v.w));
}

// ---------------- gather + mean (bf16 reads, fp32 accum) -> d_Ab ------------
// one warp per target row; lane covers 4 feature columns (8B bf16 per lane)
__global__ void gather_conv_kernel() {
    int w    = (blockIdx.x * blockDim.x + threadIdx.x) >> 5;
    int lane = threadIdx.x & 31;
    if (w >= R0) return;
    int beg = d_off0[w], end = d_off0[w + 1];
    float a0 = 0.f, a1 = 0.f, a2 = 0.f, a3 = 0.f;
    float b0 = 0.f, b1 = 0.f, b2 = 0.f, b3 = 0.f;
    int e = beg;
    for (; e + 1 < end; e += 2) {
        int s0 = d_csr0[e], s1 = d_csr0[e + 1];
        uint2 u0 = *reinterpret_cast<const uint2*>(d_xb + (size_t)s0 * NF + lane * 4);
        uint2 u1 = *reinterpret_cast<const uint2*>(d_xb + (size_t)s1 * NF + lane * 4);
        float2 p0 = __bfloat1622float2(*reinterpret_cast<__nv_bfloat162*>(&u0.x));
        float2 p1 = __bfloat1622float2(*reinterpret_cast<__nv_bfloat162*>(&u0.y));
        float2 q0 = __bfloat1622float2(*reinterpret_cast<__nv_bfloat162*>(&u1.x));
        float2 q1 = __bfloat1622float2(*reinterpret_cast<__nv_bfloat162*>(&u1.y));
        a0 += p0.x; a1 += p0.y; a2 += p1.x; a3 += p1.y;
        b0 += q0.x; b1 += q0.y; b2 += q1.x; b3 += q1.y;
    }
    if (e < end) {
        int s0 = d_csr0[e];
        uint2 u0 = *reinterpret_cast<const uint2*>(d_xb + (size_t)s0 * NF + lane * 4);
        float2 p0 = __bfloat1622float2(*reinterpret_cast<__nv_bfloat162*>(&u0.x));
        float2 p1 = __bfloat1622float2(*reinterpret_cast<__nv_bfloat162*>(&u0.y));
        a0 += p0.x; a1 += p0.y; a2 += p1.x; a3 += p1.y;
    }
    float inv = 1.f / fmaxf((float)(end - beg), 1.f);
    __nv_bfloat16* row = d_Ab + (size_t)w * 256;
    *reinterpret_cast<uint2*>(row + 128 + lane * 4) =
        make_uint2(pack_bf16((a0 + b0) * inv, (a1 + b1) * inv),
                   pack_bf16((a2 + b2) * inv, (a3 + b3) * inv));
    // root half: straight bf16 copy
    *reinterpret_cast<uint2*>(row + lane * 4) =
        *reinterpret_cast<const uint2*>(d_xb + (size_t)w * NF + lane * 4);
}

// ---------------- bf16 weight preparation -----------------------------------
__global__ void convW1_kernel(const float* __restrict__ W1r, const float* __restrict__ W1n) {
    int i = blockIdx.x * blockDim.x + threadIdx.x;
    if (i >= NHPAD * 256) return;
    int n = i >> 8, k = i & 255;
    float v = 0.f;
    if (n < NH) v = (k < 128) ? W1r[(size_t)k * NH + n] : W1n[(size_t)(k - 128) * NH + n];
    d_W1b[i] = __float2bfloat16(v);
}
__global__ void convW2_kernel(const float* __restrict__ W2n, const float* __restrict__ W2r) {
    int i = blockIdx.x * blockDim.x + threadIdx.x;
    if (i >= NC * NHPAD) return;
    int c = i / NHPAD, n = i % NHPAD;
    float vn = 0.f, vr = 0.f;
    if (n < NH) { vn = W2n[(size_t)n * NC + c]; vr = W2r[(size_t)n * NC + c]; }
    d_W2nb[i] = __float2bfloat16(vn);
    d_W2rb[i] = __float2bfloat16(vr);
}

// ---------------- HMMA helpers ----------------------------------------------
__device__ __forceinline__ void mma16816(float* c, unsigned a0, unsigned a1,
                                         unsigned a2, unsigned a3,
                                         unsigned b0, unsigned b1) {
    asm volatile(
        "mma.sync.aligned.m16n8k16.row.col.f32.bf16.bf16.f32 "
        "{%0,%1,%2,%3}, {%4,%5,%6,%7}, {%8,%9}, {%0,%1,%2,%3};"
        : "+f"(c[0]), "+f"(c[1]), "+f"(c[2]), "+f"(c[3])
        : "r"(a0), "r"(a1), "r"(a2), "r"(a3), "r"(b0), "r"(b1));
}
__device__ __forceinline__ void ldsm_x4(unsigned& r0, unsigned& r1,
                                        unsigned& r2, unsigned& r3, unsigned addr) {
    asm volatile("ldmatrix.sync.aligned.m8n8.x4.shared.b16 {%0,%1,%2,%3}, [%4];"
                 : "=r"(r0), "=r"(r1), "=r"(r2), "=r"(r3) : "r"(addr));
}

// ---------------- fused GEMM chain on HMMA tensor cores ---------------------
#define APITCH 264
#define BPITCH 264
#define WPITCH 72
#define SM_AS  0
#define SM_BS  (128 * APITCH)
#define SM_WS  (SM_BS + 64 * BPITCH)
#define SM_TOT ((SM_WS + 64 * WPITCH) * 2)     // bytes = 110592

__global__ __launch_bounds__(256, 2) void mma_fused_kernel(const float* __restrict__ b1) {
    extern __shared__ __nv_bfloat16 sm[];
    __nv_bfloat16* As = sm + SM_AS;
    __nv_bfloat16* Bs = sm + SM_BS;
    __nv_bfloat16* Ws = sm + SM_WS;
    int tid  = threadIdx.x;
    int warp = tid >> 5;
    int lane = tid & 31;
    int g    = lane >> 2;
    int tig  = lane & 3;
    int m0   = blockIdx.x * 128;
    int mrow = warp * 16;

    for (int idx = tid; idx < 128 * 32; idx += 256) {
        int row = idx >> 5, c8 = idx & 31;
        uint4 v = reinterpret_cast<const uint4*>(d_Ab + (size_t)(m0 + row) * 256)[c8];
        *reinterpret_cast<uint4*>(&As[row * APITCH + c8 * 8]) = v;
    }

    unsigned saA = (unsigned)__cvta_generic_to_shared(As);
    unsigned saB = (unsigned)__cvta_generic_to_shared(Bs);
    unsigned saW = (unsigned)__cvta_generic_to_shared(Ws);
    unsigned aBase = saA + ((mrow + (lane & 15)) * APITCH + (lane >> 4) * 8) * 2;
    unsigned bBase[4], wBase[4];
#pragma unroll
    for (int jp = 0; jp < 4; jp++) {
        int n   = jp * 16 + ((lane >> 4) & 1) * 8 + (lane & 7);
        int col = ((lane >> 3) & 1) * 8;
        bBase[jp] = saB + (n * BPITCH + col) * 2;
        wBase[jp] = saW + (n * WPITCH + col) * 2;
    }

    float accG[8][4], accY[8][4];
#pragma unroll
    for (int j = 0; j < 8; j++)
#pragma unroll
        for (int q = 0; q < 4; q++) { accG[j][q] = 0.f; accY[j][q] = 0.f; }

    const bool doY = (m0 < R1);

    for (int it = 0; it < NT; it++) {
        int n0 = it * 64;
        __syncthreads();
        for (int idx = tid; idx < 64 * 32; idx += 256) {
            int row = idx >> 5, c8 = idx & 31;
            uint4 v = reinterpret_cast<const uint4*>(d_W1b + (size_t)(n0 + row) * 256)[c8];
            *reinterpret_cast<uint4*>(&Bs[row * BPITCH + c8 * 8]) = v;
        }
        for (int idx = tid; idx < 64 * 8; idx += 256) {
            int row = idx >> 3, c8 = idx & 7;
            uint4 v = *reinterpret_cast<const uint4*>(d_W2nb + (size_t)row * NHPAD + n0 + c8 * 8);
            *reinterpret_cast<uint4*>(&Ws[row * WPITCH + c8 * 8]) = v;
        }
        __syncthreads();

        float accH[8][4];
#pragma unroll
        for (int j = 0; j < 8; j++)
#pragma unroll
            for (int q = 0; q < 4; q++) accH[j][q] = 0.f;

#pragma unroll 4
        for (int kk = 0; kk < 16; kk++) {
            unsigned a0, a1, a2, a3;
            ldsm_x4(a0, a1, a2, a3, aBase + kk * 32);
#pragma unroll
            for (int jp = 0; jp < 4; jp++) {
                unsigned r0, r1, r2, r3;
                ldsm_x4(r0, r1, r2, r3, bBase[jp] + kk * 32);
                mma16816(accH[jp * 2 + 0], a0, a1, a2, a3, r0, r1);
                mma16816(accH[jp * 2 + 1], a0, a1, a2, a3, r2, r3);
            }
        }

        unsigned hfrag[4][4];
#pragma unroll
        for (int j = 0; j < 8; j++) {
            int c0 = n0 + j * 8 + tig * 2;
            float bb0 = (c0     < NH) ? __ldg(b1 + c0)     : 0.f;
            float bb1 = (c0 + 1 < NH) ? __ldg(b1 + c0 + 1) : 0.f;
            float h0 = (c0     < NH) ? fmaxf(accH[j][0] + bb0, 0.f) : 0.f;
            float h1 = (c0 + 1 < NH) ? fmaxf(accH[j][1] + bb1, 0.f) : 0.f;
            float h2 = (c0     < NH) ? fmaxf(accH[j][2] + bb0, 0.f) : 0.f;
            float h3 = (c0 + 1 < NH) ? fmaxf(accH[j][3] + bb1, 0.f) : 0.f;
            hfrag[j >> 1][(j & 1) * 2 + 0] = pack_bf16(h0, h1);
            hfrag[j >> 1][(j & 1) * 2 + 1] = pack_bf16(h2, h3);
        }

#pragma unroll
        for (int kk = 0; kk < 4; kk++) {
            unsigned a0 = hfrag[kk][0], a1 = hfrag[kk][1];
            unsigned a2 = hfrag[kk][2], a3 = hfrag[kk][3];
#pragma unroll
            for (int jp = 0; jp < 4; jp++) {
                unsigned r0, r1, r2, r3;
                ldsm_x4(r0, r1, r2, r3, wBase[jp] + kk * 32);
                mma16816(accG[jp * 2 + 0], a0, a1, a2, a3, r0, r1);
                mma16816(accG[jp * 2 + 1], a0, a1, a2, a3, r2, r3);
            }
        }
        if (doY) {
#pragma unroll
            for (int kk = 0; kk < 4; kk++) {
                int kb = n0 + kk * 16;
                unsigned a0 = hfrag[kk][0], a1 = hfrag[kk][1];
                unsigned a2 = hfrag[kk][2], a3 = hfrag[kk][3];
#pragma unroll
                for (int j = 0; j < 8; j++) {
                    const __nv_bfloat16* bp = d_W2rb + (size_t)(j * 8 + g) * NHPAD + kb;
                    unsigned b0 = *reinterpret_cast<const unsigned*>(bp + tig * 2);
                    unsigned b1f = *reinterpret_cast<const unsigned*>(bp + 8 + tig * 2);
                    mma16816(accY[j], a0, a1, a2, a3, b0, b1f);
                }
            }
        }
    }

    {
        int gmA = m0 + mrow + g;
        int gmB = gmA + 8;
#pragma unroll
        for (int j = 0; j < 8; j++) {
            int c = j * 8 + tig * 2;
            if (gmA < R0)
                *reinterpret_cast<float2*>(d_g + (size_t)gmA * NC + c) =
                    make_float2(accG[j][0], accG[j][1]);
            if (gmB < R0)
                *reinterpret_cast<float2*>(d_g + (size_t)gmB * NC + c) =
                    make_float2(accG[j][2], accG[j][3]);
        }
        if (doY) {
#pragma unroll
            for (int j = 0; j < 8; j++) {
                int c = j * 8 + tig * 2;
                if (gmA < R1)
                    *reinterpret_cast<float2*>(d_yroot + (size_t)gmA * NC + c) =
                        make_float2(accY[j][0], accY[j][1]);
                if (gmB < R1)
                    *reinterpret_cast<float2*>(d_yroot + (size_t)gmB * NC + c) =
                        make_float2(accY[j][2], accY[j][3]);
            }
        }
    }
}

// ------- fused: gather-mean(g) + yroot + b2 + log_softmax (CSR, no atomics) -
__global__ void final_kernel(const float* __restrict__ b2, float* __restrict__ out) {
    int gid  = blockIdx.x * blockDim.x + threadIdx.x;
    int w    = gid >> 5;
    int lane = gid & 31;
    if (w >= R1) return;
    int beg = d_off1[w], end = d_off1[w + 1];
    float ax = 0.f, ay = 0.f, bx = 0.f, by = 0.f;
    int e = beg;
    for (; e + 1 < end; e += 2) {
        int s0 = d_csr1[e], s1 = d_csr1[e + 1];
        float2 v0 = *reinterpret_cast<const float2*>(d_g + (size_t)s0 * NC + lane * 2);
        float2 v1 = *reinterpret_cast<const float2*>(d_g + (size_t)s1 * NC + lane * 2);
        ax += v0.x; ay += v0.y; bx += v1.x; by += v1.y;
    }
    if (e < end) {
        int s0 = d_csr1[e];
        float2 v0 = *reinterpret_cast<const float2*>(d_g + (size_t)s0 * NC + lane * 2);
        ax += v0.x; ay += v0.y;
    }
    float inv = 1.f / fmaxf((float)(end - beg), 1.f);
    float vx = (ax + bx) * inv + d_yroot[w * NC + lane * 2 + 0] + b2[lane * 2 + 0];
    float vy = (ay + by) * inv + d_yroot[w * NC + lane * 2 + 1] + b2[lane * 2 + 1];
    float m = fmaxf(vx, vy);
#pragma unroll
    for (int o = 16; o; o >>= 1) m = fmaxf(m, __shfl_xor_sync(0xffffffffu, m, o));
    float s = expf(vx - m) + expf(vy - m);
#pragma unroll
    for (int o = 16; o; o >>= 1) s += __shfl_xor_sync(0xffffffffu, s, o);
    float lse = logf(s);
    out[w * NC + lane * 2 + 0] = vx - m - lse;
    out[w * NC + lane * 2 + 1] = vy - m - lse;
}

// ---------------- launch ----------------------------------------------------
extern "C" void kernel_launch(void* const* d_in, const int* in_sizes, int n_in,
                              void* d_out, int out_size) {
    const float *x = 0, *W1r = 0, *W1n = 0, *b1 = 0, *W2r = 0, *W2n = 0, *b2 = 0;
    const int *eA0 = 0, *eB0 = 0, *eA1 = 0, *eB1 = 0;
    for (int i = 0; i < n_in; i++) {
        int sz = in_sizes[i];
        const void* p = d_in[i];
        if      (sz == NSRC * NF) { x = (const float*)p; }
        else if (sz == NF * NH)   { if (!W1r) W1r = (const float*)p; else W1n = (const float*)p; }
        else if (sz == NH)        { b1 = (const float*)p; }
        else if (sz == NH * NC)   { if (!W2r) W2r = (const float*)p; else W2n = (const float*)p; }
        else if (sz == NC)        { b2 = (const float*)p; }
        else if (sz == E0C)       { if (!eA0) eA0 = (const int*)p; else eB0 = (const int*)p; }
        else if (sz == E1C)       { if (!eA1) eA1 = (const int*)p; else eB1 = (const int*)p; }
    }
    const int E0 = E0C, E1 = E1C;
    float* out = (float*)d_out;
    (void)out_size;

    static int smem_set = 0;
    if (!smem_set) {
        cudaFuncSetAttribute(mma_fused_kernel,
                             cudaFuncAttributeMaxDynamicSharedMemorySize, SM_TOT);
        smem_set = 1;
    }

    zero_kernel<<<(R0 + 255) / 256, 256>>>();

    edgemax_kernel<<<256, 256>>>(eA0, eB0, E0, 0);
    edgemax_kernel<<<256, 256>>>(eA1, eB1, E1, 2);

    // CSR build for both edge sets
    hist0_kernel<<<(E0 + 255) / 256, 256>>>(eA0, eB0, E0);
    hist1_kernel<<<(E1 + 255) / 256, 256>>>(eA1, eB1, E1);
    scan_kernel<<<1, 1024>>>(0);
    scan_kernel<<<1, 1024>>>(1);
    scatter0_kernel<<<(E0 + 255) / 256, 256>>>(eA0, eB0, E0);
    scatter1_kernel<<<(E1 + 255) / 256, 256>>>(eA1, eB1, E1);

    // x -> bf16, then bf16 gather straight into d_Ab
    convX_kernel<<<(int)(((size_t)NSRC * NF / 4 + 255) / 256), 256>>>(x);
    gather_conv_kernel<<<(R0 * 32 + 255) / 256, 256>>>();

    // bf16 weight prep
    convW1_kernel<<<(NHPAD * 256 + 255) / 256, 256>>>(W1r, W1n);
    convW2_kernel<<<(NC * NHPAD + 255) / 256, 256>>>(W2n, W2r);

    // fused tensor-core GEMM chain
    mma_fused_kernel<<<MTILES, 256, SM_TOT>>>(b1);

    // fused CSR gather-mean + log_softmax (replaces agg2 atomics + old final)
    final_kernel<<<(R1 * 32 + 255) / 256, 256>>>(b2, out);
}

// round 15
// speedup vs baseline: 6.7591x; 1.1021x over previous
#include <cuda_runtime.h>
#include <cuda_bf16.h>
#include <math.h>

// Problem constants (match reference setup_inputs)
#define NSRC   200000
#define NF     128
#define NH     1500
#define NC     64
#define R0     50000
#define R1     10000
#define NHPAD  1536
#define MTILES 391
#define MROWS  (MTILES * 128)   // 50048
#define NT     24               // N-slabs of 64 covering 1500 (padded to 1536)
#define E0C    1600000
#define E1C    500000

// ---------------- scratch (__device__ globals; no allocation allowed) --------
__device__ float d_g[R0 * NC];                // 12.8 MB
__device__ float d_yroot[R1 * NC];
__device__ int   d_emax[4];
__device__ int   d_cnt0[R0];
__device__ int   d_off0[R0 + 1];
__device__ int   d_cur0[R0];
__device__ int   d_csr0[E0C];
__device__ int   d_cnt1[R1];
__device__ int   d_off1[R1 + 1];
__device__ int   d_cur1[R1];
__device__ int   d_csr1[E1C];
__device__ __nv_bfloat16 d_xb[(size_t)NSRC * NF];     // 51.2 MB  x in bf16
__device__ __nv_bfloat16 d_Ab[(size_t)MROWS * 256];   // 25.6 MB  [x | xmean] bf16
__device__ __nv_bfloat16 d_W1b[NHPAD * 256];          // [n][k] = W1{r,n}[k][n]
__device__ __nv_bfloat16 d_W2nb[NC * NHPAD];          // [c][n] = W2n[n][c]
__device__ __nv_bfloat16 d_W2rb[NC * NHPAD];          // [c][n] = W2r[n][c]

__device__ __forceinline__ unsigned pack_bf16(float lo, float hi) {
    unsigned r;
    asm("cvt.rn.bf16x2.f32 %0, %1, %2;" : "=r"(r) : "f"(hi), "f"(lo));
    return r;
}

// ---------------- zero per-call-reset state (graph replays) -----------------
__global__ void zero_kernel() {
    int i = blockIdx.x * blockDim.x + threadIdx.x;
    if (i < R0) d_cnt0[i] = 0;
    if (i < R1) d_cnt1[i] = 0;
    if (i < 4)  d_emax[i] = 0;
}

// both edge pairs in one launch
__global__ void edgemax_kernel(const int* __restrict__ a0, const int* __restrict__ b0,
                               const int* __restrict__ a1, const int* __restrict__ b1) {
    __shared__ int s0, s1, s2, s3;
    if (threadIdx.x == 0) { s0 = 0; s1 = 0; s2 = 0; s3 = 0; }
    __syncthreads();
    int stride = gridDim.x * blockDim.x;
    int i0 = blockIdx.x * blockDim.x + threadIdx.x;
    int va = 0, vb = 0, vc = 0, vd = 0;
    for (int i = i0; i < E0C; i += stride) { va = max(va, a0[i]); vb = max(vb, b0[i]); }
    for (int i = i0; i < E1C; i += stride) { vc = max(vc, a1[i]); vd = max(vd, b1[i]); }
    atomicMax(&s0, va); atomicMax(&s1, vb); atomicMax(&s2, vc); atomicMax(&s3, vd);
    __syncthreads();
    if (threadIdx.x == 0) {
        atomicMax(&d_emax[0], s0); atomicMax(&d_emax[1], s1);
        atomicMax(&d_emax[2], s2); atomicMax(&d_emax[3], s3);
    }
}

// ---------------- CSR build: both layers per launch -------------------------
__global__ void hist_kernel(const int* __restrict__ eA0, const int* __restrict__ eB0,
                            const int* __restrict__ eA1, const int* __restrict__ eB1) {
    int i = blockIdx.x * blockDim.x + threadIdx.x;
    if (i < E0C) {
        bool a_is_src = d_emax[0] >= d_emax[1];
        int t = a_is_src ? eB0[i] : eA0[i];
        if ((unsigned)t < R0) atomicAdd(&d_cnt0[t], 1);
    }
    if (i < E1C) {
        bool a_is_src = d_emax[2] >= d_emax[3];
        int t = a_is_src ? eB1[i] : eA1[i];
        if ((unsigned)t < R1) atomicAdd(&d_cnt1[t], 1);
    }
}

// two blocks: blockIdx.x = which scan
__global__ void scan_kernel() {
    int which = blockIdx.x;
    const int* cnt = which ? d_cnt1 : d_cnt0;
    int* off = which ? d_off1 : d_off0;
    int* cur = which ? d_cur1 : d_cur0;
    int n    = which ? R1 : R0;
    __shared__ int buf[1024];
    __shared__ int carry;
    if (threadIdx.x == 0) carry = 0;
    __syncthreads();
    for (int base = 0; base < n; base += 1024) {
        int i = base + threadIdx.x;
        int v = (i < n) ? cnt[i] : 0;
        buf[threadIdx.x] = v;
        __syncthreads();
        for (int s = 1; s < 1024; s <<= 1) {
            int t = (threadIdx.x >= s) ? buf[threadIdx.x - s] : 0;
            __syncthreads();
            buf[threadIdx.x] += t;
            __syncthreads();
        }
        if (i < n) { int ex = carry + buf[threadIdx.x] - v; off[i] = ex; cur[i] = ex; }
        __syncthreads();
        if (threadIdx.x == 0) carry += buf[1023];
        __syncthreads();
    }
    if (threadIdx.x == 0) off[n] = carry;
}

__global__ void scatter_kernel(const int* __restrict__ eA0, const int* __restrict__ eB0,
                               const int* __restrict__ eA1, const int* __restrict__ eB1) {
    int i = blockIdx.x * blockDim.x + threadIdx.x;
    if (i < E0C) {
        bool a_is_src = d_emax[0] >= d_emax[1];
        int s = a_is_src ? eA0[i] : eB0[i];
        int t = a_is_src ? eB0[i] : eA0[i];
        if ((unsigned)t < R0 && (unsigned)s < NSRC) {
            int p = atomicAdd(&d_cur0[t], 1);
            d_csr0[p] = s;
        }
    }
    if (i < E1C) {
        bool a_is_src = d_emax[2] >= d_emax[3];
        int s = a_is_src ? eA1[i] : eB1[i];
        int t = a_is_src ? eB1[i] : eA1[i];
        if ((unsigned)t < R1 && (unsigned)s < R0) {
            int p = atomicAdd(&d_cur1[t], 1);
            d_csr1[p] = s;
        }
    }
}

// ---------------- x -> bf16 (one pass; halves gather traffic) ---------------
__global__ void convX_kernel(const float* __restrict__ x) {
    size_t i = (size_t)blockIdx.x * blockDim.x + threadIdx.x;   // one per 4 elems
    if (i >= (size_t)NSRC * NF / 4) return;
    float4 v = reinterpret_cast<const float4*>(x)[i];
    reinterpret_cast<uint2*>(d_xb)[i] =
        make_uint2(pack_bf16(v.x, v.y), pack_bf16(v.z, v.w));
}

// ---------------- gather + mean (LDG.128, 2 edges/warp in flight) -----------
// warp per target row; half-warps take alternating CSR slots; lane loads 16B.
__global__ void gather_conv_kernel() {
    int w    = (blockIdx.x * blockDim.x + threadIdx.x) >> 5;
    int lane = threadIdx.x & 31;
    if (w >= R0) return;
    int half = lane >> 4;       // 0 or 1
    int li   = lane & 15;       // 16B chunk index within row
    int beg = d_off0[w], end = d_off0[w + 1];
    float acc[8];
#pragma unroll
    for (int c = 0; c < 8; c++) acc[c] = 0.f;
    int e = beg + half;
    // ×2 unroll: two LDG.128 in flight per lane (4 edges/warp)
    for (; e + 2 < end; e += 4) {
        int s0 = d_csr0[e], s1 = d_csr0[e + 2];
        uint4 u0 = *reinterpret_cast<const uint4*>(d_xb + (size_t)s0 * NF + li * 8);
        uint4 u1 = *reinterpret_cast<const uint4*>(d_xb + (size_t)s1 * NF + li * 8);
        const unsigned* p0 = &u0.x;
        const unsigned* p1 = &u1.x;
#pragma unroll
        for (int q = 0; q < 4; q++) {
            float2 f0 = __bfloat1622float2(*reinterpret_cast<const __nv_bfloat162*>(&p0[q]));
            float2 f1 = __bfloat1622float2(*reinterpret_cast<const __nv_bfloat162*>(&p1[q]));
            acc[q * 2 + 0] += f0.x + f1.x;
            acc[q * 2 + 1] += f0.y + f1.y;
        }
    }
    for (; e < end; e += 2) {
        int s0 = d_csr0[e];
        uint4 u0 = *reinterpret_cast<const uint4*>(d_xb + (size_t)s0 * NF + li * 8);
        const unsigned* p0 = &u0.x;
#pragma unroll
        for (int q = 0; q < 4; q++) {
            float2 f0 = __bfloat1622float2(*reinterpret_cast<const __nv_bfloat162*>(&p0[q]));
            acc[q * 2 + 0] += f0.x;
            acc[q * 2 + 1] += f0.y;
        }
    }
    // combine the two halves (same li, other half)
#pragma unroll
    for (int c = 0; c < 8; c++) acc[c] += __shfl_xor_sync(0xffffffffu, acc[c], 16);
    float inv = 1.f / fmaxf((float)(end - beg), 1.f);
    __nv_bfloat16* row = d_Ab + (size_t)w * 256;
    if (half == 0) {
        unsigned r0 = pack_bf16(acc[0] * inv, acc[1] * inv);
        unsigned r1 = pack_bf16(acc[2] * inv, acc[3] * inv);
        unsigned r2 = pack_bf16(acc[4] * inv, acc[5] * inv);
        unsigned r3 = pack_bf16(acc[6] * inv, acc[7] * inv);
        *reinterpret_cast<uint4*>(row + 128 + li * 8) = make_uint4(r0, r1, r2, r3);
        // root half: straight bf16 copy (16B per lane, 16 lanes)
        *reinterpret_cast<uint4*>(row + li * 8) =
            *reinterpret_cast<const uint4*>(d_xb + (size_t)w * NF + li * 8);
    }
}

// ---------------- bf16 weight preparation (merged) --------------------------
__global__ void convW_kernel(const float* __restrict__ W1r, const float* __restrict__ W1n,
                             const float* __restrict__ W2n, const float* __restrict__ W2r) {
    int i = blockIdx.x * blockDim.x + threadIdx.x;
    if (i < NHPAD * 256) {
        int n = i >> 8, k = i & 255;
        float v = 0.f;
        if (n < NH) v = (k < 128) ? W1r[(size_t)k * NH + n] : W1n[(size_t)(k - 128) * NH + n];
        d_W1b[i] = __float2bfloat16(v);
    }
    if (i < NC * NHPAD) {
        int c = i / NHPAD, n = i % NHPAD;
        float vn = 0.f, vr = 0.f;
        if (n < NH) { vn = W2n[(size_t)n * NC + c]; vr = W2r[(size_t)n * NC + c]; }
        d_W2nb[i] = __float2bfloat16(vn);
        d_W2rb[i] = __float2bfloat16(vr);
    }
}

// ---------------- HMMA helpers ----------------------------------------------
__device__ __forceinline__ void mma16816(float* c, unsigned a0, unsigned a1,
                                         unsigned a2, unsigned a3,
                                         unsigned b0, unsigned b1) {
    asm volatile(
        "mma.sync.aligned.m16n8k16.row.col.f32.bf16.bf16.f32 "
        "{%0,%1,%2,%3}, {%4,%5,%6,%7}, {%8,%9}, {%0,%1,%2,%3};"
        : "+f"(c[0]), "+f"(c[1]), "+f"(c[2]), "+f"(c[3])
        : "r"(a0), "r"(a1), "r"(a2), "r"(a3), "r"(b0), "r"(b1));
}
__device__ __forceinline__ void ldsm_x4(unsigned& r0, unsigned& r1,
                                        unsigned& r2, unsigned& r3, unsigned addr) {
    asm volatile("ldmatrix.sync.aligned.m8n8.x4.shared.b16 {%0,%1,%2,%3}, [%4];"
                 : "=r"(r0), "=r"(r1), "=r"(r2), "=r"(r3) : "r"(addr));
}

// ---------------- fused GEMM chain on HMMA tensor cores ---------------------
#define APITCH 264
#define BPITCH 264
#define WPITCH 72
#define SM_AS  0
#define SM_BS  (128 * APITCH)
#define SM_WS  (SM_BS + 64 * BPITCH)
#define SM_TOT ((SM_WS + 64 * WPITCH) * 2)     // bytes = 110592

__global__ __launch_bounds__(256, 2) void mma_fused_kernel(const float* __restrict__ b1) {
    extern __shared__ __nv_bfloat16 sm[];
    __nv_bfloat16* As = sm + SM_AS;
    __nv_bfloat16* Bs = sm + SM_BS;
    __nv_bfloat16* Ws = sm + SM_WS;
    int tid  = threadIdx.x;
    int warp = tid >> 5;
    int lane = tid & 31;
    int g    = lane >> 2;
    int tig  = lane & 3;
    int m0   = blockIdx.x * 128;
    int mrow = warp * 16;

    for (int idx = tid; idx < 128 * 32; idx += 256) {
        int row = idx >> 5, c8 = idx & 31;
        uint4 v = reinterpret_cast<const uint4*>(d_Ab + (size_t)(m0 + row) * 256)[c8];
        *reinterpret_cast<uint4*>(&As[row * APITCH + c8 * 8]) = v;
    }

    unsigned saA = (unsigned)__cvta_generic_to_shared(As);
    unsigned saB = (unsigned)__cvta_generic_to_shared(Bs);
    unsigned saW = (unsigned)__cvta_generic_to_shared(Ws);
    unsigned aBase = saA + ((mrow + (lane & 15)) * APITCH + (lane >> 4) * 8) * 2;
    unsigned bBase[4], wBase[4];
#pragma unroll
    for (int jp = 0; jp < 4; jp++) {
        int n   = jp * 16 + ((lane >> 4) & 1) * 8 + (lane & 7);
        int col = ((lane >> 3) & 1) * 8;
        bBase[jp] = saB + (n * BPITCH + col) * 2;
        wBase[jp] = saW + (n * WPITCH + col) * 2;
    }

    float accG[8][4], accY[8][4];
#pragma unroll
    for (int j = 0; j < 8; j++)
#pragma unroll
        for (int q = 0; q < 4; q++) { accG[j][q] = 0.f; accY[j][q] = 0.f; }

    const bool doY = (m0 < R1);

    for (int it = 0; it < NT; it++) {
        int n0 = it * 64;
        __syncthreads();
        for (int idx = tid; idx < 64 * 32; idx += 256) {
            int row = idx >> 5, c8 = idx & 31;
            uint4 v = reinterpret_cast<const uint4*>(d_W1b + (size_t)(n0 + row) * 256)[c8];
            *reinterpret_cast<uint4*>(&Bs[row * BPITCH + c8 * 8]) = v;
        }
        for (int idx = tid; idx < 64 * 8; idx += 256) {
            int row = idx >> 3, c8 = idx & 7;
            uint4 v = *reinterpret_cast<const uint4*>(d_W2nb + (size_t)row * NHPAD + n0 + c8 * 8);
            *reinterpret_cast<uint4*>(&Ws[row * WPITCH + c8 * 8]) = v;
        }
        __syncthreads();

        float accH[8][4];
#pragma unroll
        for (int j = 0; j < 8; j++)
#pragma unroll
            for (int q = 0; q < 4; q++) accH[j][q] = 0.f;

#pragma unroll 4
        for (int kk = 0; kk < 16; kk++) {
            unsigned a0, a1, a2, a3;
            ldsm_x4(a0, a1, a2, a3, aBase + kk * 32);
#pragma unroll
            for (int jp = 0; jp < 4; jp++) {
                unsigned r0, r1, r2, r3;
                ldsm_x4(r0, r1, r2, r3, bBase[jp] + kk * 32);
                mma16816(accH[jp * 2 + 0], a0, a1, a2, a3, r0, r1);
                mma16816(accH[jp * 2 + 1], a0, a1, a2, a3, r2, r3);
            }
        }

        unsigned hfrag[4][4];
#pragma unroll
        for (int j = 0; j < 8; j++) {
            int c0 = n0 + j * 8 + tig * 2;
            float bb0 = (c0     < NH) ? __ldg(b1 + c0)     : 0.f;
            float bb1 = (c0 + 1 < NH) ? __ldg(b1 + c0 + 1) : 0.f;
            float h0 = (c0     < NH) ? fmaxf(accH[j][0] + bb0, 0.f) : 0.f;
            float h1 = (c0 + 1 < NH) ? fmaxf(accH[j][1] + bb1, 0.f) : 0.f;
            float h2 = (c0     < NH) ? fmaxf(accH[j][2] + bb0, 0.f) : 0.f;
            float h3 = (c0 + 1 < NH) ? fmaxf(accH[j][3] + bb1, 0.f) : 0.f;
            hfrag[j >> 1][(j & 1) * 2 + 0] = pack_bf16(h0, h1);
            hfrag[j >> 1][(j & 1) * 2 + 1] = pack_bf16(h2, h3);
        }

#pragma unroll
        for (int kk = 0; kk < 4; kk++) {
            unsigned a0 = hfrag[kk][0], a1 = hfrag[kk][1];
            unsigned a2 = hfrag[kk][2], a3 = hfrag[kk][3];
#pragma unroll
            for (int jp = 0; jp < 4; jp++) {
                unsigned r0, r1, r2, r3;
                ldsm_x4(r0, r1, r2, r3, wBase[jp] + kk * 32);
                mma16816(accG[jp * 2 + 0], a0, a1, a2, a3, r0, r1);
                mma16816(accG[jp * 2 + 1], a0, a1, a2, a3, r2, r3);
            }
        }
        if (doY) {
#pragma unroll
            for (int kk = 0; kk < 4; kk++) {
                int kb = n0 + kk * 16;
                unsigned a0 = hfrag[kk][0], a1 = hfrag[kk][1];
                unsigned a2 = hfrag[kk][2], a3 = hfrag[kk][3];
#pragma unroll
                for (int j = 0; j < 8; j++) {
                    const __nv_bfloat16* bp = d_W2rb + (size_t)(j * 8 + g) * NHPAD + kb;
                    unsigned b0 = *reinterpret_cast<const unsigned*>(bp + tig * 2);
                    unsigned b1f = *reinterpret_cast<const unsigned*>(bp + 8 + tig * 2);
                    mma16816(accY[j], a0, a1, a2, a3, b0, b1f);
                }
            }
        }
    }

    {
        int gmA = m0 + mrow + g;
        int gmB = gmA + 8;
#pragma unroll
        for (int j = 0; j < 8; j++) {
            int c = j * 8 + tig * 2;
            if (gmA < R0)
                *reinterpret_cast<float2*>(d_g + (size_t)gmA * NC + c) =
                    make_float2(accG[j][0], accG[j][1]);
            if (gmB < R0)
                *reinterpret_cast<float2*>(d_g + (size_t)gmB * NC + c) =
                    make_float2(accG[j][2], accG[j][3]);
        }
        if (doY) {
#pragma unroll
            for (int j = 0; j < 8; j++) {
                int c = j * 8 + tig * 2;
                if (gmA < R1)
                    *reinterpret_cast<float2*>(d_yroot + (size_t)gmA * NC + c) =
                        make_float2(accY[j][0], accY[j][1]);
                if (gmB < R1)
                    *reinterpret_cast<float2*>(d_yroot + (size_t)gmB * NC + c) =
                        make_float2(accY[j][2], accY[j][3]);
            }
        }
    }
}

// ------- fused: gather-mean(g) + yroot + b2 + log_softmax (CSR, no atomics) -
__global__ void final_kernel(const float* __restrict__ b2, float* __restrict__ out) {
    int gid  = blockIdx.x * blockDim.x + threadIdx.x;
    int w    = gid >> 5;
    int lane = gid & 31;
    if (w >= R1) return;
    int beg = d_off1[w], end = d_off1[w + 1];
    float ax = 0.f, ay = 0.f, bx = 0.f, by = 0.f;
    int e = beg;
    for (; e + 1 < end; e += 2) {
        int s0 = d_csr1[e], s1 = d_csr1[e + 1];
        float2 v0 = *reinterpret_cast<const float2*>(d_g + (size_t)s0 * NC + lane * 2);
        float2 v1 = *reinterpret_cast<const float2*>(d_g + (size_t)s1 * NC + lane * 2);
        ax += v0.x; ay += v0.y; bx += v1.x; by += v1.y;
    }
    if (e < end) {
        int s0 = d_csr1[e];
        float2 v0 = *reinterpret_cast<const float2*>(d_g + (size_t)s0 * NC + lane * 2);
        ax += v0.x; ay += v0.y;
    }
    float inv = 1.f / fmaxf((float)(end - beg), 1.f);
    float vx = (ax + bx) * inv + d_yroot[w * NC + lane * 2 + 0] + b2[lane * 2 + 0];
    float vy = (ay + by) * inv + d_yroot[w * NC + lane * 2 + 1] + b2[lane * 2 + 1];
    float m = fmaxf(vx, vy);
#pragma unroll
    for (int o = 16; o; o >>= 1) m = fmaxf(m, __shfl_xor_sync(0xffffffffu, m, o));
    float s = expf(vx - m) + expf(vy - m);
#pragma unroll
    for (int o = 16; o; o >>= 1) s += __shfl_xor_sync(0xffffffffu, s, o);
    float lse = logf(s);
    out[w * NC + lane * 2 + 0] = vx - m - lse;
    out[w * NC + lane * 2 + 1] = vy - m - lse;
}

// ---------------- launch ----------------------------------------------------
extern "C" void kernel_launch(void* const* d_in, const int* in_sizes, int n_in,
                              void* d_out, int out_size) {
    const float *x = 0, *W1r = 0, *W1n = 0, *b1 = 0, *W2r = 0, *W2n = 0, *b2 = 0;
    const int *eA0 = 0, *eB0 = 0, *eA1 = 0, *eB1 = 0;
    for (int i = 0; i < n_in; i++) {
        int sz = in_sizes[i];
        const void* p = d_in[i];
        if      (sz == NSRC * NF) { x = (const float*)p; }
        else if (sz == NF * NH)   { if (!W1r) W1r = (const float*)p; else W1n = (const float*)p; }
        else if (sz == NH)        { b1 = (const float*)p; }
        else if (sz == NH * NC)   { if (!W2r) W2r = (const float*)p; else W2n = (const float*)p; }
        else if (sz == NC)        { b2 = (const float*)p; }
        else if (sz == E0C)       { if (!eA0) eA0 = (const int*)p; else eB0 = (const int*)p; }
        else if (sz == E1C)       { if (!eA1) eA1 = (const int*)p; else eB1 = (const int*)p; }
    }
    float* out = (float*)d_out;
    (void)out_size;

    static int smem_set = 0;
    if (!smem_set) {
        cudaFuncSetAttribute(mma_fused_kernel,
                             cudaFuncAttributeMaxDynamicSharedMemorySize, SM_TOT);
        smem_set = 1;
    }

    zero_kernel<<<(R0 + 255) / 256, 256>>>();
    edgemax_kernel<<<256, 256>>>(eA0, eB0, eA1, eB1);

    // CSR build (both layers per launch)
    hist_kernel<<<(E0C + 255) / 256, 256>>>(eA0, eB0, eA1, eB1);
    scan_kernel<<<2, 1024>>>();
    scatter_kernel<<<(E0C + 255) / 256, 256>>>(eA0, eB0, eA1, eB1);

    // x -> bf16, then LDG.128 gather straight into d_Ab
    convX_kernel<<<(int)(((size_t)NSRC * NF / 4 + 255) / 256), 256>>>(x);
    gather_conv_kernel<<<(R0 * 32 + 255) / 256, 256>>>();

    // bf16 weight prep (merged)
    convW_kernel<<<(NHPAD * 256 + 255) / 256, 256>>>(W1r, W1n, W2n, W2r);

    // fused tensor-core GEMM chain
    mma_fused_kernel<<<MTILES, 256, SM_TOT>>>(b1);

    // fused CSR gather-mean + log_softmax
    final_kernel<<<(R1 * 32 + 255) / 256, 256>>>(b2, out);
}

// round 16
// speedup vs baseline: 7.9031x; 1.1693x over previous
#include <cuda_runtime.h>
#include <cuda_bf16.h>
#include <math.h>

// Problem constants (match reference setup_inputs)
#define NSRC   200000
#define NF     128
#define NH     1500
#define NC     64
#define R0     50000
#define R1     10000
#define NHPAD  1536
#define MTILES 391
#define MROWS  (MTILES * 128)   // 50048
#define NT     24               // N-slabs of 64 covering 1500 (padded to 1536)
#define E0C    1600000
#define E1C    500000
#define TILES0 49               // ceil(R0/1024)
#define TILES1 10               // ceil(R1/1024)
#define NTILES (TILES0 + TILES1)

// ---------------- scratch (__device__ globals; no allocation allowed) --------
__device__ float d_g[R0 * NC];                // 12.8 MB
__device__ float d_yroot[R1 * NC];
__device__ int   d_emax[4];
__device__ int   d_cnt0[R0];
__device__ int   d_off0[R0 + 1];
__device__ int   d_cur0[R0];
__device__ int   d_csr0[E0C];
__device__ int   d_cnt1[R1];
__device__ int   d_off1[R1 + 1];
__device__ int   d_cur1[R1];
__device__ int   d_csr1[E1C];
__device__ int   d_tileagg[NTILES];
__device__ int   d_tilebase[NTILES];
__device__ __nv_bfloat16 d_xb[(size_t)NSRC * NF];     // 51.2 MB  x in bf16
__device__ __nv_bfloat16 d_Ab[(size_t)MROWS * 256];   // 25.6 MB  [x | xmean] bf16
__device__ __nv_bfloat16 d_W1b[NHPAD * 256];          // [n][k] = W1{r,n}[k][n]
__device__ __nv_bfloat16 d_W2nb[NC * NHPAD];          // [c][n] = W2n[n][c]
__device__ __nv_bfloat16 d_W2rb[NC * NHPAD];          // [c][n] = W2r[n][c]

__device__ __forceinline__ unsigned pack_bf16(float lo, float hi) {
    unsigned r;
    asm("cvt.rn.bf16x2.f32 %0, %1, %2;" : "=r"(r) : "f"(hi), "f"(lo));
    return r;
}

// ---------------- zero per-call-reset state (graph replays) -----------------
__global__ void zero_kernel() {
    int i = blockIdx.x * blockDim.x + threadIdx.x;
    if (i < R0) d_cnt0[i] = 0;
    if (i < R1) d_cnt1[i] = 0;
    if (i < 4)  d_emax[i] = 0;
}

// both edge pairs in one launch
__global__ void edgemax_kernel(const int* __restrict__ a0, const int* __restrict__ b0,
                               const int* __restrict__ a1, const int* __restrict__ b1) {
    __shared__ int s0, s1, s2, s3;
    if (threadIdx.x == 0) { s0 = 0; s1 = 0; s2 = 0; s3 = 0; }
    __syncthreads();
    int stride = gridDim.x * blockDim.x;
    int i0 = blockIdx.x * blockDim.x + threadIdx.x;
    int va = 0, vb = 0, vc = 0, vd = 0;
    for (int i = i0; i < E0C; i += stride) { va = max(va, a0[i]); vb = max(vb, b0[i]); }
    for (int i = i0; i < E1C; i += stride) { vc = max(vc, a1[i]); vd = max(vd, b1[i]); }
    atomicMax(&s0, va); atomicMax(&s1, vb); atomicMax(&s2, vc); atomicMax(&s3, vd);
    __syncthreads();
    if (threadIdx.x == 0) {
        atomicMax(&d_emax[0], s0); atomicMax(&d_emax[1], s1);
        atomicMax(&d_emax[2], s2); atomicMax(&d_emax[3], s3);
    }
}

// ---------------- CSR build: both layers per launch -------------------------
__global__ void hist_kernel(const int* __restrict__ eA0, const int* __restrict__ eB0,
                            const int* __restrict__ eA1, const int* __restrict__ eB1) {
    int i = blockIdx.x * blockDim.x + threadIdx.x;
    if (i < E0C) {
        bool a_is_src = d_emax[0] >= d_emax[1];
        int t = a_is_src ? eB0[i] : eA0[i];
        if ((unsigned)t < R0) atomicAdd(&d_cnt0[t], 1);
    }
    if (i < E1C) {
        bool a_is_src = d_emax[2] >= d_emax[3];
        int t = a_is_src ? eB1[i] : eA1[i];
        if ((unsigned)t < R1) atomicAdd(&d_cnt1[t], 1);
    }
}

// ------- 3-phase parallel scan (replaces 85us 2-block Hillis-Steele) --------
// phase 1: per-tile shuffle scan; writes tile-local exclusive offs + aggregate
__global__ void scan_local_kernel() {
    int b = blockIdx.x;
    int which = (b < TILES0) ? 0 : 1;
    int tile  = which ? (b - TILES0) : b;
    const int* cnt = which ? d_cnt1 : d_cnt0;
    int* off = which ? d_off1 : d_off0;
    int n    = which ? R1 : R0;
    int tid  = threadIdx.x;
    int lane = tid & 31, wid = tid >> 5;
    int idx  = tile * 1024 + tid;
    int v = (idx < n) ? cnt[idx] : 0;
    int incl = v;
#pragma unroll
    for (int o = 1; o < 32; o <<= 1) {
        int t = __shfl_up_sync(0xffffffffu, incl, o);
        if (lane >= o) incl += t;
    }
    __shared__ int wsum[32];
    if (lane == 31) wsum[wid] = incl;
    __syncthreads();
    if (wid == 0) {
        int w = wsum[lane];
        int wi = w;
#pragma unroll
        for (int o = 1; o < 32; o <<= 1) {
            int t = __shfl_up_sync(0xffffffffu, wi, o);
            if (lane >= o) wi += t;
        }
        wsum[lane] = wi - w;               // exclusive warp base
        if (lane == 31) d_tileagg[b] = wi; // tile total
    }
    __syncthreads();
    if (idx < n) off[idx] = wsum[wid] + incl - v;
}

// phase 2: tiny serial spine over tile aggregates (49 + 10 adds)
__global__ void scan_spine_kernel() {
    if (threadIdx.x == 0) {
        int run = 0;
        for (int t = 0; t < TILES0; t++) { d_tilebase[t] = run; run += d_tileagg[t]; }
        d_off0[R0] = run;
    } else if (threadIdx.x == 1) {
        int run = 0;
        for (int t = 0; t < TILES1; t++) {
            d_tilebase[TILES0 + t] = run;
            run += d_tileagg[TILES0 + t];
        }
        d_off1[R1] = run;
    }
}

// phase 3: add tile base, init cursors
__global__ void scan_add_kernel() {
    int b = blockIdx.x;
    int which = (b < TILES0) ? 0 : 1;
    int tile  = which ? (b - TILES0) : b;
    int* off = which ? d_off1 : d_off0;
    int* cur = which ? d_cur1 : d_cur0;
    int n    = which ? R1 : R0;
    int idx = tile * 1024 + threadIdx.x;
    if (idx < n) {
        int o = off[idx] + d_tilebase[b];
        off[idx] = o;
        cur[idx] = o;
    }
}

__global__ void scatter_kernel(const int* __restrict__ eA0, const int* __restrict__ eB0,
                               const int* __restrict__ eA1, const int* __restrict__ eB1) {
    int i = blockIdx.x * blockDim.x + threadIdx.x;
    if (i < E0C) {
        bool a_is_src = d_emax[0] >= d_emax[1];
        int s = a_is_src ? eA0[i] : eB0[i];
        int t = a_is_src ? eB0[i] : eA0[i];
        if ((unsigned)t < R0 && (unsigned)s < NSRC) {
            int p = atomicAdd(&d_cur0[t], 1);
            d_csr0[p] = s;
        }
    }
    if (i < E1C) {
        bool a_is_src = d_emax[2] >= d_emax[3];
        int s = a_is_src ? eA1[i] : eB1[i];
        int t = a_is_src ? eB1[i] : eA1[i];
        if ((unsigned)t < R1 && (unsigned)s < R0) {
            int p = atomicAdd(&d_cur1[t], 1);
            d_csr1[p] = s;
        }
    }
}

// ---------------- x -> bf16 (one pass; halves gather traffic) ---------------
__global__ void convX_kernel(const float* __restrict__ x) {
    size_t i = (size_t)blockIdx.x * blockDim.x + threadIdx.x;   // one per 4 elems
    if (i >= (size_t)NSRC * NF / 4) return;
    float4 v = reinterpret_cast<const float4*>(x)[i];
    reinterpret_cast<uint2*>(d_xb)[i] =
        make_uint2(pack_bf16(v.x, v.y), pack_bf16(v.z, v.w));
}

// ---------------- gather + mean (LDG.128, 2 edges/warp in flight) -----------
__global__ void gather_conv_kernel() {
    int w    = (blockIdx.x * blockDim.x + threadIdx.x) >> 5;
    int lane = threadIdx.x & 31;
    if (w >= R0) return;
    int half = lane >> 4;       // 0 or 1
    int li   = lane & 15;       // 16B chunk index within row
    int beg = d_off0[w], end = d_off0[w + 1];
    float acc[8];
#pragma unroll
    for (int c = 0; c < 8; c++) acc[c] = 0.f;
    int e = beg + half;
    for (; e + 2 < end; e += 4) {
        int s0 = d_csr0[e], s1 = d_csr0[e + 2];
        uint4 u0 = *reinterpret_cast<const uint4*>(d_xb + (size_t)s0 * NF + li * 8);
        uint4 u1 = *reinterpret_cast<const uint4*>(d_xb + (size_t)s1 * NF + li * 8);
        const unsigned* p0 = &u0.x;
        const unsigned* p1 = &u1.x;
#pragma unroll
        for (int q = 0; q < 4; q++) {
            float2 f0 = __bfloat1622float2(*reinterpret_cast<const __nv_bfloat162*>(&p0[q]));
            float2 f1 = __bfloat1622float2(*reinterpret_cast<const __nv_bfloat162*>(&p1[q]));
            acc[q * 2 + 0] += f0.x + f1.x;
            acc[q * 2 + 1] += f0.y + f1.y;
        }
    }
    for (; e < end; e += 2) {
        int s0 = d_csr0[e];
        uint4 u0 = *reinterpret_cast<const uint4*>(d_xb + (size_t)s0 * NF + li * 8);
        const unsigned* p0 = &u0.x;
#pragma unroll
        for (int q = 0; q < 4; q++) {
            float2 f0 = __bfloat1622float2(*reinterpret_cast<const __nv_bfloat162*>(&p0[q]));
            acc[q * 2 + 0] += f0.x;
            acc[q * 2 + 1] += f0.y;
        }
    }
#pragma unroll
    for (int c = 0; c < 8; c++) acc[c] += __shfl_xor_sync(0xffffffffu, acc[c], 16);
    float inv = 1.f / fmaxf((float)(end - beg), 1.f);
    __nv_bfloat16* row = d_Ab + (size_t)w * 256;
    if (half == 0) {
        unsigned r0 = pack_bf16(acc[0] * inv, acc[1] * inv);
        unsigned r1 = pack_bf16(acc[2] * inv, acc[3] * inv);
        unsigned r2 = pack_bf16(acc[4] * inv, acc[5] * inv);
        unsigned r3 = pack_bf16(acc[6] * inv, acc[7] * inv);
        *reinterpret_cast<uint4*>(row + 128 + li * 8) = make_uint4(r0, r1, r2, r3);
        *reinterpret_cast<uint4*>(row + li * 8) =
            *reinterpret_cast<const uint4*>(d_xb + (size_t)w * NF + li * 8);
    }
}

// ---------------- bf16 weight preparation (merged) --------------------------
__global__ void convW_kernel(const float* __restrict__ W1r, const float* __restrict__ W1n,
                             const float* __restrict__ W2n, const float* __restrict__ W2r) {
    int i = blockIdx.x * blockDim.x + threadIdx.x;
    if (i < NHPAD * 256) {
        int n = i >> 8, k = i & 255;
        float v = 0.f;
        if (n < NH) v = (k < 128) ? W1r[(size_t)k * NH + n] : W1n[(size_t)(k - 128) * NH + n];
        d_W1b[i] = __float2bfloat16(v);
    }
    if (i < NC * NHPAD) {
        int c = i / NHPAD, n = i % NHPAD;
        float vn = 0.f, vr = 0.f;
        if (n < NH) { vn = W2n[(size_t)n * NC + c]; vr = W2r[(size_t)n * NC + c]; }
        d_W2nb[i] = __float2bfloat16(vn);
        d_W2rb[i] = __float2bfloat16(vr);
    }
}

// ---------------- HMMA helpers ----------------------------------------------
__device__ __forceinline__ void mma16816(float* c, unsigned a0, unsigned a1,
                                         unsigned a2, unsigned a3,
                                         unsigned b0, unsigned b1) {
    asm volatile(
        "mma.sync.aligned.m16n8k16.row.col.f32.bf16.bf16.f32 "
        "{%0,%1,%2,%3}, {%4,%5,%6,%7}, {%8,%9}, {%0,%1,%2,%3};"
        : "+f"(c[0]), "+f"(c[1]), "+f"(c[2]), "+f"(c[3])
        : "r"(a0), "r"(a1), "r"(a2), "r"(a3), "r"(b0), "r"(b1));
}
__device__ __forceinline__ void ldsm_x4(unsigned& r0, unsigned& r1,
                                        unsigned& r2, unsigned& r3, unsigned addr) {
    asm volatile("ldmatrix.sync.aligned.m8n8.x4.shared.b16 {%0,%1,%2,%3}, [%4];"
                 : "=r"(r0), "=r"(r1), "=r"(r2), "=r"(r3) : "r"(addr));
}

// ---------------- fused GEMM chain on HMMA tensor cores ---------------------
#define APITCH 264
#define BPITCH 264
#define WPITCH 72
#define SM_AS  0
#define SM_BS  (128 * APITCH)
#define SM_WS  (SM_BS + 64 * BPITCH)
#define SM_TOT ((SM_WS + 64 * WPITCH) * 2)     // bytes = 110592

__global__ __launch_bounds__(256, 2) void mma_fused_kernel(const float* __restrict__ b1) {
    extern __shared__ __nv_bfloat16 sm[];
    __nv_bfloat16* As = sm + SM_AS;
    __nv_bfloat16* Bs = sm + SM_BS;
    __nv_bfloat16* Ws = sm + SM_WS;
    int tid  = threadIdx.x;
    int warp = tid >> 5;
    int lane = tid & 31;
    int g    = lane >> 2;
    int tig  = lane & 3;
    int m0   = blockIdx.x * 128;
    int mrow = warp * 16;

    for (int idx = tid; idx < 128 * 32; idx += 256) {
        int row = idx >> 5, c8 = idx & 31;
        uint4 v = reinterpret_cast<const uint4*>(d_Ab + (size_t)(m0 + row) * 256)[c8];
        *reinterpret_cast<uint4*>(&As[row * APITCH + c8 * 8]) = v;
    }

    unsigned saA = (unsigned)__cvta_generic_to_shared(As);
    unsigned saB = (unsigned)__cvta_generic_to_shared(Bs);
    unsigned saW = (unsigned)__cvta_generic_to_shared(Ws);
    unsigned aBase = saA + ((mrow + (lane & 15)) * APITCH + (lane >> 4) * 8) * 2;
    unsigned bBase[4], wBase[4];
#pragma unroll
    for (int jp = 0; jp < 4; jp++) {
        int n   = jp * 16 + ((lane >> 4) & 1) * 8 + (lane & 7);
        int col = ((lane >> 3) & 1) * 8;
        bBase[jp] = saB + (n * BPITCH + col) * 2;
        wBase[jp] = saW + (n * WPITCH + col) * 2;
    }

    float accG[8][4], accY[8][4];
#pragma unroll
    for (int j = 0; j < 8; j++)
#pragma unroll
        for (int q = 0; q < 4; q++) { accG[j][q] = 0.f; accY[j][q] = 0.f; }

    const bool doY = (m0 < R1);

    for (int it = 0; it < NT; it++) {
        int n0 = it * 64;
        __syncthreads();
        for (int idx = tid; idx < 64 * 32; idx += 256) {
            int row = idx >> 5, c8 = idx & 31;
            uint4 v = reinterpret_cast<const uint4*>(d_W1b + (size_t)(n0 + row) * 256)[c8];
            *reinterpret_cast<uint4*>(&Bs[row * BPITCH + c8 * 8]) = v;
        }
        for (int idx = tid; idx < 64 * 8; idx += 256) {
            int row = idx >> 3, c8 = idx & 7;
            uint4 v = *reinterpret_cast<const uint4*>(d_W2nb + (size_t)row * NHPAD + n0 + c8 * 8);
            *reinterpret_cast<uint4*>(&Ws[row * WPITCH + c8 * 8]) = v;
        }
        __syncthreads();

        float accH[8][4];
#pragma unroll
        for (int j = 0; j < 8; j++)
#pragma unroll
            for (int q = 0; q < 4; q++) accH[j][q] = 0.f;

#pragma unroll 4
        for (int kk = 0; kk < 16; kk++) {
            unsigned a0, a1, a2, a3;
            ldsm_x4(a0, a1, a2, a3, aBase + kk * 32);
#pragma unroll
            for (int jp = 0; jp < 4; jp++) {
                unsigned r0, r1, r2, r3;
                ldsm_x4(r0, r1, r2, r3, bBase[jp] + kk * 32);
                mma16816(accH[jp * 2 + 0], a0, a1, a2, a3, r0, r1);
                mma16816(accH[jp * 2 + 1], a0, a1, a2, a3, r2, r3);
            }
        }

        unsigned hfrag[4][4];
#pragma unroll
        for (int j = 0; j < 8; j++) {
            int c0 = n0 + j * 8 + tig * 2;
            float bb0 = (c0     < NH) ? __ldg(b1 + c0)     : 0.f;
            float bb1 = (c0 + 1 < NH) ? __ldg(b1 + c0 + 1) : 0.f;
            float h0 = (c0     < NH) ? fmaxf(accH[j][0] + bb0, 0.f) : 0.f;
            float h1 = (c0 + 1 < NH) ? fmaxf(accH[j][1] + bb1, 0.f) : 0.f;
            float h2 = (c0     < NH) ? fmaxf(accH[j][2] + bb0, 0.f) : 0.f;
            float h3 = (c0 + 1 < NH) ? fmaxf(accH[j][3] + bb1, 0.f) : 0.f;
            hfrag[j >> 1][(j & 1) * 2 + 0] = pack_bf16(h0, h1);
            hfrag[j >> 1][(j & 1) * 2 + 1] = pack_bf16(h2, h3);
        }

#pragma unroll
        for (int kk = 0; kk < 4; kk++) {
            unsigned a0 = hfrag[kk][0], a1 = hfrag[kk][1];
            unsigned a2 = hfrag[kk][2], a3 = hfrag[kk][3];
#pragma unroll
            for (int jp = 0; jp < 4; jp++) {
                unsigned r0, r1, r2, r3;
                ldsm_x4(r0, r1, r2, r3, wBase[jp] + kk * 32);
                mma16816(accG[jp * 2 + 0], a0, a1, a2, a3, r0, r1);
                mma16816(accG[jp * 2 + 1], a0, a1, a2, a3, r2, r3);
            }
        }
        if (doY) {
#pragma unroll
            for (int kk = 0; kk < 4; kk++) {
                int kb = n0 + kk * 16;
                unsigned a0 = hfrag[kk][0], a1 = hfrag[kk][1];
                unsigned a2 = hfrag[kk][2], a3 = hfrag[kk][3];
#pragma unroll
                for (int j = 0; j < 8; j++) {
                    const __nv_bfloat16* bp = d_W2rb + (size_t)(j * 8 + g) * NHPAD + kb;
                    unsigned b0 = *reinterpret_cast<const unsigned*>(bp + tig * 2);
                    unsigned b1f = *reinterpret_cast<const unsigned*>(bp + 8 + tig * 2);
                    mma16816(accY[j], a0, a1, a2, a3, b0, b1f);
                }
            }
        }
    }

    {
        int gmA = m0 + mrow + g;
        int gmB = gmA + 8;
#pragma unroll
        for (int j = 0; j < 8; j++) {
            int c = j * 8 + tig * 2;
            if (gmA < R0)
                *reinterpret_cast<float2*>(d_g + (size_t)gmA * NC + c) =
                    make_float2(accG[j][0], accG[j][1]);
            if (gmB < R0)
                *reinterpret_cast<float2*>(d_g + (size_t)gmB * NC + c) =
                    make_float2(accG[j][2], accG[j][3]);
        }
        if (doY) {
#pragma unroll
            for (int j = 0; j < 8; j++) {
                int c = j * 8 + tig * 2;
                if (gmA < R1)
                    *reinterpret_cast<float2*>(d_yroot + (size_t)gmA * NC + c) =
                        make_float2(accY[j][0], accY[j][1]);
                if (gmB < R1)
                    *reinterpret_cast<float2*>(d_yroot + (size_t)gmB * NC + c) =
                        make_float2(accY[j][2], accY[j][3]);
            }
        }
    }
}

// ------- fused: gather-mean(g) + yroot + b2 + log_softmax (CSR, no atomics) -
__global__ void final_kernel(const float* __restrict__ b2, float* __restrict__ out) {
    int gid  = blockIdx.x * blockDim.x + threadIdx.x;
    int w    = gid >> 5;
    int lane = gid & 31;
    if (w >= R1) return;
    int beg = d_off1[w], end = d_off1[w + 1];
    float ax = 0.f, ay = 0.f, bx = 0.f, by = 0.f;
    int e = beg;
    for (; e + 1 < end; e += 2) {
        int s0 = d_csr1[e], s1 = d_csr1[e + 1];
        float2 v0 = *reinterpret_cast<const float2*>(d_g + (size_t)s0 * NC + lane * 2);
        float2 v1 = *reinterpret_cast<const float2*>(d_g + (size_t)s1 * NC + lane * 2);
        ax += v0.x; ay += v0.y; bx += v1.x; by += v1.y;
    }
    if (e < end) {
        int s0 = d_csr1[e];
        float2 v0 = *reinterpret_cast<const float2*>(d_g + (size_t)s0 * NC + lane * 2);
        ax += v0.x; ay += v0.y;
    }
    float inv = 1.f / fmaxf((float)(end - beg), 1.f);
    float vx = (ax + bx) * inv + d_yroot[w * NC + lane * 2 + 0] + b2[lane * 2 + 0];
    float vy = (ay + by) * inv + d_yroot[w * NC + lane * 2 + 1] + b2[lane * 2 + 1];
    float m = fmaxf(vx, vy);
#pragma unroll
    for (int o = 16; o; o >>= 1) m = fmaxf(m, __shfl_xor_sync(0xffffffffu, m, o));
    float s = expf(vx - m) + expf(vy - m);
#pragma unroll
    for (int o = 16; o; o >>= 1) s += __shfl_xor_sync(0xffffffffu, s, o);
    float lse = logf(s);
    out[w * NC + lane * 2 + 0] = vx - m - lse;
    out[w * NC + lane * 2 + 1] = vy - m - lse;
}

// ---------------- launch ----------------------------------------------------
extern "C" void kernel_launch(void* const* d_in, const int* in_sizes, int n_in,
                              void* d_out, int out_size) {
    const float *x = 0, *W1r = 0, *W1n = 0, *b1 = 0, *W2r = 0, *W2n = 0, *b2 = 0;
    const int *eA0 = 0, *eB0 = 0, *eA1 = 0, *eB1 = 0;
    for (int i = 0; i < n_in; i++) {
        int sz = in_sizes[i];
        const void* p = d_in[i];
        if      (sz == NSRC * NF) { x = (const float*)p; }
        else if (sz == NF * NH)   { if (!W1r) W1r = (const float*)p; else W1n = (const float*)p; }
        else if (sz == NH)        { b1 = (const float*)p; }
        else if (sz == NH * NC)   { if (!W2r) W2r = (const float*)p; else W2n = (const float*)p; }
        else if (sz == NC)        { b2 = (const float*)p; }
        else if (sz == E0C)       { if (!eA0) eA0 = (const int*)p; else eB0 = (const int*)p; }
        else if (sz == E1C)       { if (!eA1) eA1 = (const int*)p; else eB1 = (const int*)p; }
    }
    float* out = (float*)d_out;
    (void)out_size;

    static int smem_set = 0;
    if (!smem_set) {
        cudaFuncSetAttribute(mma_fused_kernel,
                             cudaFuncAttributeMaxDynamicSharedMemorySize, SM_TOT);
        smem_set = 1;
    }

    zero_kernel<<<(R0 + 255) / 256, 256>>>();
    edgemax_kernel<<<256, 256>>>(eA0, eB0, eA1, eB1);

    // CSR build (both layers per launch); 3-phase parallel scan
    hist_kernel<<<(E0C + 255) / 256, 256>>>(eA0, eB0, eA1, eB1);
    scan_local_kernel<<<NTILES, 1024>>>();
    scan_spine_kernel<<<1, 64>>>();
    scan_add_kernel<<<NTILES, 1024>>>();
    scatter_kernel<<<(E0C + 255) / 256, 256>>>(eA0, eB0, eA1, eB1);

    // x -> bf16, then LDG.128 gather straight into d_Ab
    convX_kernel<<<(int)(((size_t)NSRC * NF / 4 + 255) / 256), 256>>>(x);
    gather_conv_kernel<<<(R0 * 32 + 255) / 256, 256>>>();

    // bf16 weight prep (merged)
    convW_kernel<<<(NHPAD * 256 + 255) / 256, 256>>>(W1r, W1n, W2n, W2r);

    // fused tensor-core GEMM chain
    mma_fused_kernel<<<MTILES, 256, SM_TOT>>>(b1);

    // fused CSR gather-mean + log_softmax
    final_kernel<<<(R1 * 32 + 255) / 256, 256>>>(b2, out);
}